// round 3
// baseline (speedup 1.0000x reference)
#include <cuda_runtime.h>
#include <math.h>

// Problem dims (fixed for this dataset)
static constexpr int Bsz = 16384;
static constexpr int Hd  = 512;   // H == D == 512
static constexpr long long BH = (long long)Bsz * Hd;   // 8388608

// -------- scratch (device globals: allocation-free rule) --------
__device__ float2 g_px [3ull * Bsz * Hd];   // px[k][b][h] complex, k=0..2   (201 MB)
__device__ float2 g_pzr[2ull * Bsz * Hd];   // pz, pr                       (134 MB)
__device__ float2 g_z  [(unsigned long long)Bsz * Hd];   // gate z          (67 MB)
__device__ float2 g_ph [(unsigned long long)Bsz * Hd];   // (r*h)@Wh2 + bh2 (67 MB)
__device__ float  g_rh_re[(unsigned long long)Bsz * Hd]; // r*h real plane  (33 MB)
__device__ float  g_rh_im[(unsigned long long)Bsz * Hd]; // r*h imag plane  (33 MB)

// -------- packed f32x2 helpers (FFMA2 path, sm_103a) --------
__device__ __forceinline__ unsigned long long pack2(float lo, float hi) {
    unsigned long long r;
    asm("mov.b64 %0, {%1, %2};" : "=l"(r) : "f"(lo), "f"(hi));
    return r;
}
__device__ __forceinline__ void unpack2(unsigned long long v, float& lo, float& hi) {
    asm("mov.b64 {%0, %1}, %2;" : "=f"(lo), "=f"(hi) : "l"(v));
}
__device__ __forceinline__ void fma2(unsigned long long& d, unsigned long long a, unsigned long long b) {
    asm("fma.rn.f32x2 %0, %1, %2, %0;" : "+l"(d) : "l"(a), "l"(b));
}

// ======================= complex GEMM =======================
// C[g][m][n] = sum_k A[m][k] * W[g][n][k]  + bias[g][n]      (complex)
// A given as separate re/im planes [B x K]; W as re/im planes [G x N x K].
// Accumulator packed as (re, im) in one 64-bit reg; per complex MAC:
//   acc += (a_re,a_re) * (w_re, w_im)          (FFMA2)
//   acc += (a_im,a_im) * (-w_im, w_re)         (FFMA2)
#define BM 64
#define BN 128
#define BKT 16
#define TM 4
#define TN 8
// threads = (BM/TM) * (BN/TN) = 16 * 16 = 256

__global__ __launch_bounds__(256)
void cgemm_kernel(const float* __restrict__ A_re, const float* __restrict__ A_im,
                  const float* __restrict__ W_re, const float* __restrict__ W_im,
                  const float* __restrict__ b_re, const float* __restrict__ b_im,
                  float2* __restrict__ C,
                  int K, int N, long long gate_stride)
{
    __shared__ float2 sA[BKT * BM];           // (a_re, a_im), indexed [k][m]   8 KB
    __shared__ float4 sW[BKT * BN];           // (w_re, w_im, -w_im, w_re)     32 KB

    const int g   = blockIdx.z;
    const int mb  = blockIdx.y * BM;
    const int nb  = blockIdx.x * BN;
    const int tid = threadIdx.x;
    const int tx  = tid & 15;                 // n-group
    const int ty  = tid >> 4;                 // m-group

    // A-load mapping: 64 rows x 4 k-groups(of 4) = 256 float4 per plane
    const int a_m  = tid >> 2;                // 0..63
    const int a_k4 = (tid & 3) * 4;           // 0,4,8,12
    // W-load mapping: 128 rows x 4 k-groups = 512 float4 per plane -> 2 per thread
    const int w_n0 = tid >> 2;                // 0..63   (group 0)
    const int w_n1 = 64 + (tid >> 2);         //         (group 1)
    const int w_k4 = (tid & 3) * 4;

    unsigned long long acc[TM][TN];
#pragma unroll
    for (int i = 0; i < TM; i++)
#pragma unroll
        for (int j = 0; j < TN; j++) acc[i][j] = 0ull;  // bits of (0.f, 0.f)

    const float* Wrg = W_re + (size_t)g * N * K;
    const float* Wig = W_im + (size_t)g * N * K;

    for (int k0 = 0; k0 < K; k0 += BKT) {
        // ---- global loads (registers) ----
        float4 ar = *(const float4*)&A_re[(size_t)(mb + a_m) * K + k0 + a_k4];
        float4 ai = *(const float4*)&A_im[(size_t)(mb + a_m) * K + k0 + a_k4];
        float4 wr0 = *(const float4*)&Wrg[(size_t)(nb + w_n0) * K + k0 + w_k4];
        float4 wi0 = *(const float4*)&Wig[(size_t)(nb + w_n0) * K + k0 + w_k4];
        float4 wr1 = *(const float4*)&Wrg[(size_t)(nb + w_n1) * K + k0 + w_k4];
        float4 wi1 = *(const float4*)&Wig[(size_t)(nb + w_n1) * K + k0 + w_k4];

        __syncthreads();   // previous tile fully consumed

        // ---- stage to smem ----
        {
            const float* arf = (const float*)&ar;
            const float* aif = (const float*)&ai;
#pragma unroll
            for (int kk = 0; kk < 4; kk++)
                sA[(a_k4 + kk) * BM + a_m] = make_float2(arf[kk], aif[kk]);

            const float* w0r = (const float*)&wr0; const float* w0i = (const float*)&wi0;
            const float* w1r = (const float*)&wr1; const float* w1i = (const float*)&wi1;
#pragma unroll
            for (int kk = 0; kk < 4; kk++) {
                sW[(w_k4 + kk) * BN + w_n0] = make_float4(w0r[kk], w0i[kk], -w0i[kk], w0r[kk]);
                sW[(w_k4 + kk) * BN + w_n1] = make_float4(w1r[kk], w1i[kk], -w1i[kk], w1r[kk]);
            }
        }
        __syncthreads();

        // ---- compute ----
#pragma unroll
        for (int kk = 0; kk < BKT; kk++) {
            const float4* pa = (const float4*)&sA[kk * BM + ty * TM];
            float4 a01 = pa[0];
            float4 a23 = pa[1];
            unsigned long long arr[TM], aim[TM];
            arr[0] = pack2(a01.x, a01.x); aim[0] = pack2(a01.y, a01.y);
            arr[1] = pack2(a01.z, a01.z); aim[1] = pack2(a01.w, a01.w);
            arr[2] = pack2(a23.x, a23.x); aim[2] = pack2(a23.y, a23.y);
            arr[3] = pack2(a23.z, a23.z); aim[3] = pack2(a23.w, a23.w);
#pragma unroll
            for (int j = 0; j < TN; j++) {
                float4 wv = sW[kk * BN + tx + 16 * j];   // conflict-free: lanes consecutive
                unsigned long long wri = pack2(wv.x, wv.y);
                unsigned long long wmr = pack2(wv.z, wv.w);
#pragma unroll
                for (int i = 0; i < TM; i++) {
                    fma2(acc[i][j], arr[i], wri);
                    fma2(acc[i][j], aim[i], wmr);
                }
            }
        }
    }

    // ---- epilogue: bias + store ----
    float2* Cg = C + (size_t)g * gate_stride;
#pragma unroll
    for (int j = 0; j < TN; j++) {
        int n = nb + tx + 16 * j;
        float br = b_re[g * N + n];
        float bi = b_im[g * N + n];
#pragma unroll
        for (int i = 0; i < TM; i++) {
            int m = mb + ty * TM + i;
            float cr, ci;
            unpack2(acc[i][j], cr, ci);
            Cg[(size_t)m * N + n] = make_float2(cr + br, ci + bi);
        }
    }
}

// ======================= elementwise kernels =======================
__device__ __forceinline__ float sigm(float x) { return 1.0f / (1.0f + expf(-x)); }

__global__ void gates_kernel(const float* __restrict__ h_re, const float* __restrict__ h_im,
                             const float2* __restrict__ px, const float2* __restrict__ pzr,
                             float2* __restrict__ zout,
                             float* __restrict__ rh_re, float* __restrict__ rh_im)
{
    long long i = blockIdx.x * (long long)blockDim.x + threadIdx.x;
    if (i >= BH) return;
    float2 p0 = px[i];
    float2 p1 = px[BH + i];
    float2 q0 = pzr[i];
    float2 q1 = pzr[BH + i];
    float zr = sigm(p0.x + q0.x);
    float zi = sigm(p0.y + q0.y);
    float rr = sigm(p1.x + q1.x);
    float ri = sigm(p1.y + q1.y);
    float hr = h_re[i], hi = h_im[i];
    zout[i]  = make_float2(zr, zi);
    rh_re[i] = rr * hr - ri * hi;     // complex r*h
    rh_im[i] = rr * hi + ri * hr;
}

__global__ void final_kernel(const float* __restrict__ h_re, const float* __restrict__ h_im,
                             const float2* __restrict__ px2, const float2* __restrict__ ph,
                             const float2* __restrict__ zin, float2* __restrict__ out)
{
    long long i = blockIdx.x * (long long)blockDim.x + threadIdx.x;
    if (i >= BH) return;
    float2 p = px2[i];
    float2 q = ph[i];
    float tr = p.x + q.x, ti = p.y + q.y;
    float mag = sqrtf(tr * tr + ti * ti);
    float s = (mag > 0.0f) ? (tanhf(mag) / mag) : 1.0f;   // polar tanh scale
    float htr = s * tr, hti = s * ti;
    float2 z = zin[i];
    float hr = h_re[i], hi = h_im[i];
    float or_ = 1.0f - z.x, oi = -z.y;                    // (1 - z) complex
    float hnr = or_ * hr - oi * hi + z.x * htr - z.y * hti;
    float hni = or_ * hi + oi * hr + z.x * hti + z.y * htr;
    out[i] = make_float2(hnr, hni);                       // [B,H,2] float
}

// ======================= launch =======================
extern "C" void kernel_launch(void* const* d_in, const int* in_sizes, int n_in,
                              void* d_out, int out_size)
{
    const float* x_re  = (const float*)d_in[0];
    const float* x_im  = (const float*)d_in[1];
    const float* h_re  = (const float*)d_in[2];
    const float* h_im  = (const float*)d_in[3];
    const float* Wx_re = (const float*)d_in[4];
    const float* Wx_im = (const float*)d_in[5];
    const float* Wh_re = (const float*)d_in[6];
    const float* Wh_im = (const float*)d_in[7];
    const float* bx_re = (const float*)d_in[8];
    const float* bx_im = (const float*)d_in[9];
    const float* bh_re = (const float*)d_in[10];
    const float* bh_im = (const float*)d_in[11];

    float2* px;   cudaGetSymbolAddress((void**)&px,   g_px);
    float2* pzr;  cudaGetSymbolAddress((void**)&pzr,  g_pzr);
    float2* zbuf; cudaGetSymbolAddress((void**)&zbuf, g_z);
    float2* ph;   cudaGetSymbolAddress((void**)&ph,   g_ph);
    float*  rhre; cudaGetSymbolAddress((void**)&rhre, g_rh_re);
    float*  rhim; cudaGetSymbolAddress((void**)&rhim, g_rh_im);

    const int K = Hd, N = Hd;
    dim3 blk(256);
    dim3 grid_px(N / BN, Bsz / BM, 3);
    dim3 grid_zr(N / BN, Bsz / BM, 2);
    dim3 grid_h (N / BN, Bsz / BM, 1);
    dim3 eblk(256);
    dim3 egrid((unsigned)(BH / 256));

    // 1) px[k] = x @ Wx[k]^T + bx[k]   (k = 0..2)
    cgemm_kernel<<<grid_px, blk>>>(x_re, x_im, Wx_re, Wx_im, bx_re, bx_im, px, K, N, BH);
    // 2) pz, pr = h @ Wh[0,1]^T + bh[0,1]
    cgemm_kernel<<<grid_zr, blk>>>(h_re, h_im, Wh_re, Wh_im, bh_re, bh_im, pzr, K, N, BH);
    // 3) z, r, r*h
    gates_kernel<<<egrid, eblk>>>(h_re, h_im, px, pzr, zbuf, rhre, rhim);
    // 4) ph = (r*h) @ Wh[2]^T + bh[2]
    cgemm_kernel<<<grid_h, blk>>>(rhre, rhim,
                                  Wh_re + 2ull * N * K, Wh_im + 2ull * N * K,
                                  bh_re + 2 * N, bh_im + 2 * N, ph, K, N, BH);
    // 5) h_tilde, h_new
    final_kernel<<<egrid, eblk>>>(h_re, h_im, px + 2 * BH, ph, zbuf, (float2*)d_out);
}

// round 6
// speedup vs baseline: 1.0004x; 1.0004x over previous
#include <cuda_runtime.h>
#include <math.h>

// Problem dims (fixed for this dataset)
static constexpr int Bsz = 16384;
static constexpr int Hd  = 512;   // H == D == 512
static constexpr long long BH = (long long)Bsz * Hd;   // 8388608

// -------- scratch (device globals: allocation-free rule) --------
__device__ float2 g_px [3ull * Bsz * Hd];   // px[k][b][h] complex, k=0..2   (201 MB)
__device__ float2 g_pzr[2ull * Bsz * Hd];   // pz, pr                       (134 MB)
__device__ float2 g_z  [(unsigned long long)Bsz * Hd];   // gate z          (67 MB)
__device__ float2 g_ph [(unsigned long long)Bsz * Hd];   // (r*h)@Wh2 + bh2 (67 MB)
__device__ float  g_rh_re[(unsigned long long)Bsz * Hd]; // r*h real plane  (33 MB)
__device__ float  g_rh_im[(unsigned long long)Bsz * Hd]; // r*h imag plane  (33 MB)

// -------- packed f32x2 helpers (FFMA2 path, sm_103a) --------
__device__ __forceinline__ unsigned long long pack2(float lo, float hi) {
    unsigned long long r;
    asm("mov.b64 %0, {%1, %2};" : "=l"(r) : "f"(lo), "f"(hi));
    return r;
}
__device__ __forceinline__ void unpack2(unsigned long long v, float& lo, float& hi) {
    asm("mov.b64 {%0, %1}, %2;" : "=f"(lo), "=f"(hi) : "l"(v));
}
__device__ __forceinline__ void fma2(unsigned long long& d, unsigned long long a, unsigned long long b) {
    asm("fma.rn.f32x2 %0, %1, %2, %0;" : "+l"(d) : "l"(a), "l"(b));
}

// ======================= complex GEMM =======================
// C[g][m][n] = sum_k A[m][k] * W[g][n][k]  + bias[g][n]      (complex)
// A given as separate re/im planes [B x K]; W as re/im planes [G x N x K].
// Accumulator packed as (re, im) in one 64-bit reg; per complex MAC:
//   acc += (a_re,a_re) * (w_re, w_im)          (FFMA2)
//   acc += (a_im,a_im) * (-w_im, w_re)         (FFMA2)
#define BM 64
#define BN 128
#define BKT 16
#define TM 4
#define TN 8
// threads = (BM/TM) * (BN/TN) = 16 * 16 = 256

__global__ __launch_bounds__(256)
void cgemm_kernel(const float* __restrict__ A_re, const float* __restrict__ A_im,
                  const float* __restrict__ W_re, const float* __restrict__ W_im,
                  const float* __restrict__ b_re, const float* __restrict__ b_im,
                  float2* __restrict__ C,
                  int K, int N, long long gate_stride)
{
    __shared__ float2 sA[BKT * BM];           // (a_re, a_im), indexed [k][m]   8 KB
    __shared__ float4 sW[BKT * BN];           // (w_re, w_im, -w_im, w_re)     32 KB

    const int g   = blockIdx.z;
    const int mb  = blockIdx.y * BM;
    const int nb  = blockIdx.x * BN;
    const int tid = threadIdx.x;
    const int tx  = tid & 15;                 // n-group
    const int ty  = tid >> 4;                 // m-group

    // A-load mapping: 64 rows x 4 k-groups(of 4) = 256 float4 per plane
    const int a_m  = tid >> 2;                // 0..63
    const int a_k4 = (tid & 3) * 4;           // 0,4,8,12
    // W-load mapping: 128 rows x 4 k-groups = 512 float4 per plane -> 2 per thread
    const int w_n0 = tid >> 2;                // 0..63   (group 0)
    const int w_n1 = 64 + (tid >> 2);         //         (group 1)
    const int w_k4 = (tid & 3) * 4;

    unsigned long long acc[TM][TN];
#pragma unroll
    for (int i = 0; i < TM; i++)
#pragma unroll
        for (int j = 0; j < TN; j++) acc[i][j] = 0ull;  // bits of (0.f, 0.f)

    const float* Wrg = W_re + (size_t)g * N * K;
    const float* Wig = W_im + (size_t)g * N * K;

    for (int k0 = 0; k0 < K; k0 += BKT) {
        // ---- global loads (registers) ----
        float4 ar = *(const float4*)&A_re[(size_t)(mb + a_m) * K + k0 + a_k4];
        float4 ai = *(const float4*)&A_im[(size_t)(mb + a_m) * K + k0 + a_k4];
        float4 wr0 = *(const float4*)&Wrg[(size_t)(nb + w_n0) * K + k0 + w_k4];
        float4 wi0 = *(const float4*)&Wig[(size_t)(nb + w_n0) * K + k0 + w_k4];
        float4 wr1 = *(const float4*)&Wrg[(size_t)(nb + w_n1) * K + k0 + w_k4];
        float4 wi1 = *(const float4*)&Wig[(size_t)(nb + w_n1) * K + k0 + w_k4];

        __syncthreads();   // previous tile fully consumed

        // ---- stage to smem ----
        {
            const float* arf = (const float*)&ar;
            const float* aif = (const float*)&ai;
#pragma unroll
            for (int kk = 0; kk < 4; kk++)
                sA[(a_k4 + kk) * BM + a_m] = make_float2(arf[kk], aif[kk]);

            const float* w0r = (const float*)&wr0; const float* w0i = (const float*)&wi0;
            const float* w1r = (const float*)&wr1; const float* w1i = (const float*)&wi1;
#pragma unroll
            for (int kk = 0; kk < 4; kk++) {
                sW[(w_k4 + kk) * BN + w_n0] = make_float4(w0r[kk], w0i[kk], -w0i[kk], w0r[kk]);
                sW[(w_k4 + kk) * BN + w_n1] = make_float4(w1r[kk], w1i[kk], -w1i[kk], w1r[kk]);
            }
        }
        __syncthreads();

        // ---- compute ----
#pragma unroll
        for (int kk = 0; kk < BKT; kk++) {
            const float4* pa = (const float4*)&sA[kk * BM + ty * TM];
            float4 a01 = pa[0];
            float4 a23 = pa[1];
            unsigned long long arr[TM], aim[TM];
            arr[0] = pack2(a01.x, a01.x); aim[0] = pack2(a01.y, a01.y);
            arr[1] = pack2(a01.z, a01.z); aim[1] = pack2(a01.w, a01.w);
            arr[2] = pack2(a23.x, a23.x); aim[2] = pack2(a23.y, a23.y);
            arr[3] = pack2(a23.z, a23.z); aim[3] = pack2(a23.w, a23.w);
#pragma unroll
            for (int j = 0; j < TN; j++) {
                float4 wv = sW[kk * BN + tx + 16 * j];   // conflict-free: lanes consecutive
                unsigned long long wri = pack2(wv.x, wv.y);
                unsigned long long wmr = pack2(wv.z, wv.w);
#pragma unroll
                for (int i = 0; i < TM; i++) {
                    fma2(acc[i][j], arr[i], wri);
                    fma2(acc[i][j], aim[i], wmr);
                }
            }
        }
    }

    // ---- epilogue: bias + store ----
    float2* Cg = C + (size_t)g * gate_stride;
#pragma unroll
    for (int j = 0; j < TN; j++) {
        int n = nb + tx + 16 * j;
        float br = b_re[g * N + n];
        float bi = b_im[g * N + n];
#pragma unroll
        for (int i = 0; i < TM; i++) {
            int m = mb + ty * TM + i;
            float cr, ci;
            unpack2(acc[i][j], cr, ci);
            Cg[(size_t)m * N + n] = make_float2(cr + br, ci + bi);
        }
    }
}

// ======================= elementwise kernels =======================
__device__ __forceinline__ float sigm(float x) { return 1.0f / (1.0f + expf(-x)); }

__global__ void gates_kernel(const float* __restrict__ h_re, const float* __restrict__ h_im,
                             const float2* __restrict__ px, const float2* __restrict__ pzr,
                             float2* __restrict__ zout,
                             float* __restrict__ rh_re, float* __restrict__ rh_im)
{
    long long i = blockIdx.x * (long long)blockDim.x + threadIdx.x;
    if (i >= BH) return;
    float2 p0 = px[i];
    float2 p1 = px[BH + i];
    float2 q0 = pzr[i];
    float2 q1 = pzr[BH + i];
    float zr = sigm(p0.x + q0.x);
    float zi = sigm(p0.y + q0.y);
    float rr = sigm(p1.x + q1.x);
    float ri = sigm(p1.y + q1.y);
    float hr = h_re[i], hi = h_im[i];
    zout[i]  = make_float2(zr, zi);
    rh_re[i] = rr * hr - ri * hi;     // complex r*h
    rh_im[i] = rr * hi + ri * hr;
}

__global__ void final_kernel(const float* __restrict__ h_re, const float* __restrict__ h_im,
                             const float2* __restrict__ px2, const float2* __restrict__ ph,
                             const float2* __restrict__ zin, float2* __restrict__ out)
{
    long long i = blockIdx.x * (long long)blockDim.x + threadIdx.x;
    if (i >= BH) return;
    float2 p = px2[i];
    float2 q = ph[i];
    float tr = p.x + q.x, ti = p.y + q.y;
    float mag = sqrtf(tr * tr + ti * ti);
    float s = (mag > 0.0f) ? (tanhf(mag) / mag) : 1.0f;   // polar tanh scale
    float htr = s * tr, hti = s * ti;
    float2 z = zin[i];
    float hr = h_re[i], hi = h_im[i];
    float or_ = 1.0f - z.x, oi = -z.y;                    // (1 - z) complex
    float hnr = or_ * hr - oi * hi + z.x * htr - z.y * hti;
    float hni = or_ * hi + oi * hr + z.x * hti + z.y * htr;
    out[i] = make_float2(hnr, hni);                       // [B,H,2] float
}

// ======================= launch =======================
extern "C" void kernel_launch(void* const* d_in, const int* in_sizes, int n_in,
                              void* d_out, int out_size)
{
    const float* x_re  = (const float*)d_in[0];
    const float* x_im  = (const float*)d_in[1];
    const float* h_re  = (const float*)d_in[2];
    const float* h_im  = (const float*)d_in[3];
    const float* Wx_re = (const float*)d_in[4];
    const float* Wx_im = (const float*)d_in[5];
    const float* Wh_re = (const float*)d_in[6];
    const float* Wh_im = (const float*)d_in[7];
    const float* bx_re = (const float*)d_in[8];
    const float* bx_im = (const float*)d_in[9];
    const float* bh_re = (const float*)d_in[10];
    const float* bh_im = (const float*)d_in[11];

    float2* px;   cudaGetSymbolAddress((void**)&px,   g_px);
    float2* pzr;  cudaGetSymbolAddress((void**)&pzr,  g_pzr);
    float2* zbuf; cudaGetSymbolAddress((void**)&zbuf, g_z);
    float2* ph;   cudaGetSymbolAddress((void**)&ph,   g_ph);
    float*  rhre; cudaGetSymbolAddress((void**)&rhre, g_rh_re);
    float*  rhim; cudaGetSymbolAddress((void**)&rhim, g_rh_im);

    const int K = Hd, N = Hd;
    dim3 blk(256);
    dim3 grid_px(N / BN, Bsz / BM, 3);
    dim3 grid_zr(N / BN, Bsz / BM, 2);
    dim3 grid_h (N / BN, Bsz / BM, 1);
    dim3 eblk(256);
    dim3 egrid((unsigned)(BH / 256));

    // 1) px[k] = x @ Wx[k]^T + bx[k]   (k = 0..2)
    cgemm_kernel<<<grid_px, blk>>>(x_re, x_im, Wx_re, Wx_im, bx_re, bx_im, px, K, N, BH);
    // 2) pz, pr = h @ Wh[0,1]^T + bh[0,1]
    cgemm_kernel<<<grid_zr, blk>>>(h_re, h_im, Wh_re, Wh_im, bh_re, bh_im, pzr, K, N, BH);
    // 3) z, r, r*h
    gates_kernel<<<egrid, eblk>>>(h_re, h_im, px, pzr, zbuf, rhre, rhim);
    // 4) ph = (r*h) @ Wh[2]^T + bh[2]
    cgemm_kernel<<<grid_h, blk>>>(rhre, rhim,
                                  Wh_re + 2ull * N * K, Wh_im + 2ull * N * K,
                                  bh_re + 2 * N, bh_im + 2 * N, ph, K, N, BH);
    // 5) h_tilde, h_new
    final_kernel<<<egrid, eblk>>>(h_re, h_im, px + 2 * BH, ph, zbuf, (float2*)d_out);
}

// round 8
// speedup vs baseline: 3.8674x; 3.8660x over previous
#include <cuda_runtime.h>
#include <cstdint>
#include <math.h>

static constexpr int Bsz = 16384;
static constexpr int Hd  = 512;
static constexpr long long BH = (long long)Bsz * Hd;   // 8388608

// -------- scratch (device globals; allocation-free rule) --------
__device__ float2 g_px [3ull * Bsz * Hd];
__device__ float2 g_pzr[2ull * Bsz * Hd];
__device__ float2 g_z  [(unsigned long long)Bsz * Hd];
__device__ float2 g_ph [(unsigned long long)Bsz * Hd];
__device__ float  g_rh_re[(unsigned long long)Bsz * Hd];
__device__ float  g_rh_im[(unsigned long long)Bsz * Hd];

// ======================= PTX helpers (base-target only) =======================
__device__ __forceinline__ uint32_t smem_u32(const void* p){
    uint32_t a;
    asm("{ .reg .u64 t; cvta.to.shared.u64 t, %1; cvt.u32.u64 %0, t; }" : "=r"(a) : "l"(p));
    return a;
}
__device__ __forceinline__ void cp16(uint32_t dst, const void* src){
    asm volatile("cp.async.cg.shared.global [%0], [%1], 16;" :: "r"(dst), "l"(src));
}
#define CP_COMMIT() asm volatile("cp.async.commit_group;" ::: "memory")
#define CP_WAIT(n)  asm volatile("cp.async.wait_group %0;" :: "n"(n) : "memory")

__device__ __forceinline__ uint32_t f2tf(float x){
    uint32_t r; asm("cvt.rna.tf32.f32 %0, %1;" : "=r"(r) : "f"(x)); return r;
}
// D += A(m16k8, row) * B(k8n8, col)  — tf32 in, f32 acc
__device__ __forceinline__ void mma8(float* c, const uint32_t* a, uint32_t b0, uint32_t b1){
    asm volatile(
        "mma.sync.aligned.m16n8k8.row.col.f32.tf32.tf32.f32 "
        "{%0,%1,%2,%3}, {%4,%5,%6,%7}, {%8,%9}, {%0,%1,%2,%3};"
        : "+f"(c[0]), "+f"(c[1]), "+f"(c[2]), "+f"(c[3])
        : "r"(a[0]), "r"(a[1]), "r"(a[2]), "r"(a[3]), "r"(b0), "r"(b1));
}

// ======================= tensor-core complex GEMM (mma.sync tf32) ============
// C[g][m][n] = sum_k A[m][k]*W[g][n][k] + b[g][n]  (complex; split re/im planes)
// CTA tile: 128(M) x 64(N); 8 warps of 32x32; K staged in chunks of 32.
static constexpr int KT = 32;                    // floats per k-chunk
static constexpr int NIT = Hd / KT;              // 16
static constexpr int RS = 36;                    // padded smem row stride (floats)
static constexpr int OAr = 0;                    // plane offsets (floats)
static constexpr int OAi = 128 * RS;             // 4608
static constexpr int OWr = 2 * 128 * RS;         // 9216
static constexpr int OWi = OWr + 64 * RS;        // 11520
static constexpr int STG_F = OWi + 64 * RS;      // 13824 floats/stage
static constexpr int STG_B = STG_F * 4;          // 55296 bytes
static constexpr int SMEM_DYN = 2 * STG_B;       // 110592

__global__ __launch_bounds__(256)
void cgemm_tc(const float* __restrict__ A_re, const float* __restrict__ A_im,
              const float* __restrict__ W_re, const float* __restrict__ W_im,
              const float* __restrict__ b_re, const float* __restrict__ b_im,
              float2* __restrict__ C, long long gate_stride)
{
    extern __shared__ __align__(16) float smf[];
    const int tid = threadIdx.x;
    const int w   = tid >> 5, l = tid & 31;
    const int gid = l >> 2, tig = l & 3;
    const int wm  = w & 3;                      // 0..3  (M position, 32 each)
    const int wn  = w >> 2;                     // 0..1  (N position, 32 each)
    const int g   = blockIdx.z;
    const int mb  = blockIdx.y * 128;
    const int nb  = blockIdx.x * 64;
    const uint32_t smb = smem_u32(smf);

    const char* Wr = (const char*)(W_re + (size_t)g * Hd * Hd);
    const char* Wi = (const char*)(W_im + (size_t)g * Hd * Hd);
    const char* Ar = (const char*)A_re;
    const char* Ai = (const char*)A_im;

    // ---- cp.async stage loader: 384 rows x 8 x 16B chunks, 12 per thread ----
    auto load_stage = [&](int kb, int st){
        const uint32_t base = smb + st * STG_B;
        const size_t kby = (size_t)kb * (KT * 4);
#pragma unroll
        for (int i = 0; i < 12; i++){
            int c   = i * 256 + tid;
            int row = c >> 3;
            int j   = (c & 7) * 16;
            if (row < 128){
                cp16(base + (OAr + row * RS) * 4 + j,           Ar + (size_t)(mb + row) * 2048 + kby + j);
            } else if (row < 256){
                int r = row - 128;
                cp16(base + (OAi + r * RS) * 4 + j,             Ai + (size_t)(mb + r) * 2048 + kby + j);
            } else if (row < 320){
                int r = row - 256;
                cp16(base + (OWr + r * RS) * 4 + j,             Wr + (size_t)(nb + r) * 2048 + kby + j);
            } else {
                int r = row - 320;
                cp16(base + (OWi + r * RS) * 4 + j,             Wi + (size_t)(nb + r) * 2048 + kby + j);
            }
        }
    };

    float accRe[2][4][4], accIm[2][4][4];
#pragma unroll
    for (int mi = 0; mi < 2; mi++)
#pragma unroll
        for (int nj = 0; nj < 4; nj++)
#pragma unroll
            for (int q = 0; q < 4; q++){ accRe[mi][nj][q] = 0.f; accIm[mi][nj][q] = 0.f; }

    load_stage(0, 0);
    CP_COMMIT();

    for (int kb = 0; kb < NIT; kb++){
        if (kb + 1 < NIT){
            load_stage(kb + 1, (kb + 1) & 1);
            CP_COMMIT();
            CP_WAIT(1);          // chunk kb resident
        } else {
            CP_WAIT(0);
        }
        __syncthreads();

        const float* st = smf + (kb & 1) * STG_F;
#pragma unroll
        for (int kc = 0; kc < 4; kc++){
            const int k0 = kc * 8;
            // A fragments (both planes), m16k8 row-major layout
            uint32_t fAr[2][4], fAi[2][4];
#pragma unroll
            for (int mi = 0; mi < 2; mi++){
                int rb = (wm * 32 + mi * 16 + gid) * RS + k0;
                fAr[mi][0] = f2tf(st[OAr + rb + tig]);
                fAr[mi][1] = f2tf(st[OAr + rb + 8 * RS + tig]);
                fAr[mi][2] = f2tf(st[OAr + rb + tig + 4]);
                fAr[mi][3] = f2tf(st[OAr + rb + 8 * RS + tig + 4]);
                fAi[mi][0] = f2tf(st[OAi + rb + tig]);
                fAi[mi][1] = f2tf(st[OAi + rb + 8 * RS + tig]);
                fAi[mi][2] = f2tf(st[OAi + rb + tig + 4]);
                fAi[mi][3] = f2tf(st[OAi + rb + 8 * RS + tig + 4]);
            }
#pragma unroll
            for (int nj = 0; nj < 4; nj++){
                int cb = (wn * 32 + nj * 8 + gid) * RS + k0;
                uint32_t br0 = f2tf(st[OWr + cb + tig]);
                uint32_t br1 = f2tf(st[OWr + cb + tig + 4]);
                uint32_t bi0 = f2tf(st[OWi + cb + tig]);
                uint32_t bi1 = f2tf(st[OWi + cb + tig + 4]);
                uint32_t bn0 = bi0 ^ 0x80000000u;   // -wi (sign flip valid for tf32)
                uint32_t bn1 = bi1 ^ 0x80000000u;
#pragma unroll
                for (int mi = 0; mi < 2; mi++){
                    mma8(accRe[mi][nj], fAr[mi], br0, br1);   // + ar*wr
                    mma8(accRe[mi][nj], fAi[mi], bn0, bn1);   // - ai*wi
                    mma8(accIm[mi][nj], fAr[mi], bi0, bi1);   // + ar*wi
                    mma8(accIm[mi][nj], fAi[mi], br0, br1);   // + ai*wr
                }
            }
        }
        __syncthreads();
    }

    // ---- epilogue: bias + interleaved (re,im) float4 stores ----
    float2* Cg = C + (size_t)g * gate_stride;
    const float* brp = b_re + (size_t)g * Hd;
    const float* bip = b_im + (size_t)g * Hd;
#pragma unroll
    for (int nj = 0; nj < 4; nj++){
        int n = nb + wn * 32 + nj * 8 + tig * 2;
        float br0 = brp[n],     bi0 = bip[n];
        float br1 = brp[n + 1], bi1 = bip[n + 1];
#pragma unroll
        for (int mi = 0; mi < 2; mi++){
            int row0 = mb + wm * 32 + mi * 16 + gid;
            float4 v0 = make_float4(accRe[mi][nj][0] + br0, accIm[mi][nj][0] + bi0,
                                    accRe[mi][nj][1] + br1, accIm[mi][nj][1] + bi1);
            *(float4*)&Cg[(size_t)row0 * Hd + n] = v0;
            float4 v1 = make_float4(accRe[mi][nj][2] + br0, accIm[mi][nj][2] + bi0,
                                    accRe[mi][nj][3] + br1, accIm[mi][nj][3] + bi1);
            *(float4*)&Cg[(size_t)(row0 + 8) * Hd + n] = v1;
        }
    }
}

// ======================= elementwise kernels =======================
__device__ __forceinline__ float sigm(float x) { return 1.0f / (1.0f + expf(-x)); }

__global__ void gates_kernel(const float* __restrict__ h_re, const float* __restrict__ h_im,
                             const float2* __restrict__ px, const float2* __restrict__ pzr,
                             float2* __restrict__ zout,
                             float* __restrict__ rh_re, float* __restrict__ rh_im)
{
    long long i = blockIdx.x * (long long)blockDim.x + threadIdx.x;
    if (i >= BH) return;
    float2 p0 = px[i], p1 = px[BH + i];
    float2 q0 = pzr[i], q1 = pzr[BH + i];
    float zr = sigm(p0.x + q0.x), zi = sigm(p0.y + q0.y);
    float rr = sigm(p1.x + q1.x), ri = sigm(p1.y + q1.y);
    float hr = h_re[i], hi = h_im[i];
    zout[i]  = make_float2(zr, zi);
    rh_re[i] = rr * hr - ri * hi;
    rh_im[i] = rr * hi + ri * hr;
}

__global__ void final_kernel(const float* __restrict__ h_re, const float* __restrict__ h_im,
                             const float2* __restrict__ px2, const float2* __restrict__ ph,
                             const float2* __restrict__ zin, float2* __restrict__ out)
{
    long long i = blockIdx.x * (long long)blockDim.x + threadIdx.x;
    if (i >= BH) return;
    float2 p = px2[i], q = ph[i];
    float tr = p.x + q.x, ti = p.y + q.y;
    float mag = sqrtf(tr * tr + ti * ti);
    float s = (mag > 0.0f) ? (tanhf(mag) / mag) : 1.0f;
    float htr = s * tr, hti = s * ti;
    float2 z = zin[i];
    float hr = h_re[i], hi = h_im[i];
    float or_ = 1.0f - z.x, oi = -z.y;
    float hnr = or_ * hr - oi * hi + z.x * htr - z.y * hti;
    float hni = or_ * hi + oi * hr + z.x * hti + z.y * htr;
    out[i] = make_float2(hnr, hni);
}

// ======================= launch =======================
extern "C" void kernel_launch(void* const* d_in, const int* in_sizes, int n_in,
                              void* d_out, int out_size)
{
    const float* x_re  = (const float*)d_in[0];
    const float* x_im  = (const float*)d_in[1];
    const float* h_re  = (const float*)d_in[2];
    const float* h_im  = (const float*)d_in[3];
    const float* Wx_re = (const float*)d_in[4];
    const float* Wx_im = (const float*)d_in[5];
    const float* Wh_re = (const float*)d_in[6];
    const float* Wh_im = (const float*)d_in[7];
    const float* bx_re = (const float*)d_in[8];
    const float* bx_im = (const float*)d_in[9];
    const float* bh_re = (const float*)d_in[10];
    const float* bh_im = (const float*)d_in[11];

    float2* px;   cudaGetSymbolAddress((void**)&px,   g_px);
    float2* pzr;  cudaGetSymbolAddress((void**)&pzr,  g_pzr);
    float2* zbuf; cudaGetSymbolAddress((void**)&zbuf, g_z);
    float2* ph;   cudaGetSymbolAddress((void**)&ph,   g_ph);
    float*  rhre; cudaGetSymbolAddress((void**)&rhre, g_rh_re);
    float*  rhim; cudaGetSymbolAddress((void**)&rhim, g_rh_im);

    cudaFuncSetAttribute(cgemm_tc, cudaFuncAttributeMaxDynamicSharedMemorySize, SMEM_DYN);

    dim3 blk(256);
    dim3 grid_px(Hd / 64, Bsz / 128, 3);
    dim3 grid_zr(Hd / 64, Bsz / 128, 2);
    dim3 grid_h (Hd / 64, Bsz / 128, 1);
    dim3 eblk(256);
    dim3 egrid((unsigned)(BH / 256));

    cgemm_tc<<<grid_px, blk, SMEM_DYN>>>(x_re, x_im, Wx_re, Wx_im, bx_re, bx_im, px, BH);
    cgemm_tc<<<grid_zr, blk, SMEM_DYN>>>(h_re, h_im, Wh_re, Wh_im, bh_re, bh_im, pzr, BH);
    gates_kernel<<<egrid, eblk>>>(h_re, h_im, px, pzr, zbuf, rhre, rhim);
    cgemm_tc<<<grid_h, blk, SMEM_DYN>>>(rhre, rhim,
                                        Wh_re + 2ull * Hd * Hd, Wh_im + 2ull * Hd * Hd,
                                        bh_re + 2 * Hd, bh_im + 2 * Hd, ph, BH);
    final_kernel<<<egrid, eblk>>>(h_re, h_im, px + 2 * BH, ph, zbuf, (float2*)d_out);
}

// round 9
// speedup vs baseline: 3.8910x; 1.0061x over previous
#include <cuda_runtime.h>
#include <cstdint>
#include <math.h>

static constexpr int Bsz = 16384;
static constexpr int Hd  = 512;
static constexpr long long BH = (long long)Bsz * Hd;   // 8388608
static constexpr int WSZ = 3 * Hd * Hd;                // per-plane W elements

// -------- scratch (device globals; allocation-free rule) --------
__device__ float2 g_px [3ull * Bsz * Hd];
__device__ float2 g_pzr[2ull * Bsz * Hd];
__device__ float2 g_z  [(unsigned long long)Bsz * Hd];
__device__ float2 g_ph [(unsigned long long)Bsz * Hd];
__device__ float  g_rh_re[(unsigned long long)Bsz * Hd];
__device__ float  g_rh_im[(unsigned long long)Bsz * Hd];
// tf32-rounded copies (prep pass)
__device__ float  g_tx_re[(unsigned long long)Bsz * Hd];
__device__ float  g_tx_im[(unsigned long long)Bsz * Hd];
__device__ float  g_th_re[(unsigned long long)Bsz * Hd];
__device__ float  g_th_im[(unsigned long long)Bsz * Hd];
__device__ float  g_tWx_re[WSZ];
__device__ float  g_tWx_im[WSZ];
__device__ float  g_tWh_re[WSZ];
__device__ float  g_tWh_im[WSZ];

// ======================= PTX helpers (base-target only) =======================
__device__ __forceinline__ uint32_t smem_u32(const void* p){
    uint32_t a;
    asm("{ .reg .u64 t; cvta.to.shared.u64 t, %1; cvt.u32.u64 %0, t; }" : "=r"(a) : "l"(p));
    return a;
}
__device__ __forceinline__ void cp16(uint32_t dst, const void* src){
    asm volatile("cp.async.cg.shared.global [%0], [%1], 16;" :: "r"(dst), "l"(src));
}
#define CP_COMMIT() asm volatile("cp.async.commit_group;" ::: "memory")
#define CP_WAIT(n)  asm volatile("cp.async.wait_group %0;" :: "n"(n) : "memory")

__device__ __forceinline__ uint32_t f2tf(float x){
    uint32_t r; asm("cvt.rna.tf32.f32 %0, %1;" : "=r"(r) : "f"(x)); return r;
}
// D += A(m16k8, row) * B(k8n8, col)  — tf32 in, f32 acc
__device__ __forceinline__ void mma8(float* c, const uint32_t* a, uint32_t b0, uint32_t b1){
    asm volatile(
        "mma.sync.aligned.m16n8k8.row.col.f32.tf32.tf32.f32 "
        "{%0,%1,%2,%3}, {%4,%5,%6,%7}, {%8,%9}, {%0,%1,%2,%3};"
        : "+f"(c[0]), "+f"(c[1]), "+f"(c[2]), "+f"(c[3])
        : "r"(a[0]), "r"(a[1]), "r"(a[2]), "r"(a[3]), "r"(b0), "r"(b1));
}

// ======================= tensor-core complex GEMM (mma.sync tf32) ============
// Inputs are PRE-ROUNDED to tf32 (low mantissa bits zero) — mainloop has no CVT.
// CTA tile: 128(M) x 128(N); 16 warps (4x4) of 32x32 warp tiles; K chunks of 32.
static constexpr int KT = 32;
static constexpr int NIT = Hd / KT;              // 16
static constexpr int RS = 36;                    // padded smem row stride (floats)
static constexpr int OAr = 0;                    // 128 rows
static constexpr int OAi = 128 * RS;
static constexpr int OWr = 256 * RS;
static constexpr int OWi = 384 * RS;
static constexpr int STG_F = 512 * RS;           // 18432 floats/stage
static constexpr int STG_B = STG_F * 4;          // 73728 bytes
static constexpr int SMEM_DYN = 2 * STG_B;       // 147456

__global__ __launch_bounds__(512)
void cgemm_tc(const float* __restrict__ A_re, const float* __restrict__ A_im,
              const float* __restrict__ W_re, const float* __restrict__ W_im,
              const float* __restrict__ b_re, const float* __restrict__ b_im,
              float2* __restrict__ C, long long gate_stride)
{
    extern __shared__ __align__(16) float smf[];
    const int tid = threadIdx.x;
    const int w   = tid >> 5, l = tid & 31;
    const int gid = l >> 2, tig = l & 3;
    const int wm  = w & 3;                      // 0..3  (M, 32 each)
    const int wn  = w >> 2;                     // 0..3  (N, 32 each)
    const int g   = blockIdx.z;
    const int mb  = blockIdx.y * 128;
    const int nb  = blockIdx.x * 128;
    const uint32_t smb = smem_u32(smf);

    const char* Wr = (const char*)(W_re + (size_t)g * Hd * Hd);
    const char* Wi = (const char*)(W_im + (size_t)g * Hd * Hd);
    const char* Ar = (const char*)A_re;
    const char* Ai = (const char*)A_im;

    // ---- cp.async stage loader: 512 rows x 8 x 16B chunks, 8 per thread ----
    auto load_stage = [&](int kb, int st){
        const uint32_t base = smb + st * STG_B;
        const size_t kby = (size_t)kb * (KT * 4);
#pragma unroll
        for (int i = 0; i < 8; i++){
            int c   = i * 512 + tid;
            int row = c >> 3;
            int j   = (c & 7) * 16;
            if (row < 128){
                cp16(base + (OAr + row * RS) * 4 + j, Ar + (size_t)(mb + row) * 2048 + kby + j);
            } else if (row < 256){
                int r = row - 128;
                cp16(base + (OAi + r * RS) * 4 + j,   Ai + (size_t)(mb + r) * 2048 + kby + j);
            } else if (row < 384){
                int r = row - 256;
                cp16(base + (OWr + r * RS) * 4 + j,   Wr + (size_t)(nb + r) * 2048 + kby + j);
            } else {
                int r = row - 384;
                cp16(base + (OWi + r * RS) * 4 + j,   Wi + (size_t)(nb + r) * 2048 + kby + j);
            }
        }
    };

    float accRe[2][4][4], accIm[2][4][4];
#pragma unroll
    for (int mi = 0; mi < 2; mi++)
#pragma unroll
        for (int nj = 0; nj < 4; nj++)
#pragma unroll
            for (int q = 0; q < 4; q++){ accRe[mi][nj][q] = 0.f; accIm[mi][nj][q] = 0.f; }

    load_stage(0, 0);
    CP_COMMIT();

    for (int kb = 0; kb < NIT; kb++){
        if (kb + 1 < NIT){
            load_stage(kb + 1, (kb + 1) & 1);
            CP_COMMIT();
            CP_WAIT(1);
        } else {
            CP_WAIT(0);
        }
        __syncthreads();

        const float* st = smf + (kb & 1) * STG_F;
#pragma unroll
        for (int kc = 0; kc < 4; kc++){
            const int k0 = kc * 8;
            uint32_t fAr[2][4], fAi[2][4];
#pragma unroll
            for (int mi = 0; mi < 2; mi++){
                int rb = (wm * 32 + mi * 16 + gid) * RS + k0;
                fAr[mi][0] = __float_as_uint(st[OAr + rb + tig]);
                fAr[mi][1] = __float_as_uint(st[OAr + rb + 8 * RS + tig]);
                fAr[mi][2] = __float_as_uint(st[OAr + rb + tig + 4]);
                fAr[mi][3] = __float_as_uint(st[OAr + rb + 8 * RS + tig + 4]);
                fAi[mi][0] = __float_as_uint(st[OAi + rb + tig]);
                fAi[mi][1] = __float_as_uint(st[OAi + rb + 8 * RS + tig]);
                fAi[mi][2] = __float_as_uint(st[OAi + rb + tig + 4]);
                fAi[mi][3] = __float_as_uint(st[OAi + rb + 8 * RS + tig + 4]);
            }
#pragma unroll
            for (int nj = 0; nj < 4; nj++){
                int cb = (wn * 32 + nj * 8 + gid) * RS + k0;
                uint32_t br0 = __float_as_uint(st[OWr + cb + tig]);
                uint32_t br1 = __float_as_uint(st[OWr + cb + tig + 4]);
                uint32_t bi0 = __float_as_uint(st[OWi + cb + tig]);
                uint32_t bi1 = __float_as_uint(st[OWi + cb + tig + 4]);
                uint32_t bn0 = bi0 ^ 0x80000000u;   // -wi
                uint32_t bn1 = bi1 ^ 0x80000000u;
#pragma unroll
                for (int mi = 0; mi < 2; mi++){
                    mma8(accRe[mi][nj], fAr[mi], br0, br1);
                    mma8(accRe[mi][nj], fAi[mi], bn0, bn1);
                    mma8(accIm[mi][nj], fAr[mi], bi0, bi1);
                    mma8(accIm[mi][nj], fAi[mi], br0, br1);
                }
            }
        }
        __syncthreads();
    }

    // ---- epilogue: bias + interleaved (re,im) float4 stores ----
    float2* Cg = C + (size_t)g * gate_stride;
    const float* brp = b_re + (size_t)g * Hd;
    const float* bip = b_im + (size_t)g * Hd;
#pragma unroll
    for (int nj = 0; nj < 4; nj++){
        int n = nb + wn * 32 + nj * 8 + tig * 2;
        float br0 = brp[n],     bi0 = bip[n];
        float br1 = brp[n + 1], bi1 = bip[n + 1];
#pragma unroll
        for (int mi = 0; mi < 2; mi++){
            int row0 = mb + wm * 32 + mi * 16 + gid;
            float4 v0 = make_float4(accRe[mi][nj][0] + br0, accIm[mi][nj][0] + bi0,
                                    accRe[mi][nj][1] + br1, accIm[mi][nj][1] + bi1);
            *(float4*)&Cg[(size_t)row0 * Hd + n] = v0;
            float4 v1 = make_float4(accRe[mi][nj][2] + br0, accIm[mi][nj][2] + bi0,
                                    accRe[mi][nj][3] + br1, accIm[mi][nj][3] + bi1);
            *(float4*)&Cg[(size_t)(row0 + 8) * Hd + n] = v1;
        }
    }
}

// ======================= prep: tf32 rounding pass =======================
__global__ void round_tf32_kernel(const float4* __restrict__ src, float4* __restrict__ dst, int n4)
{
    int i = blockIdx.x * blockDim.x + threadIdx.x;
    if (i >= n4) return;
    float4 v = src[i];
    v.x = __uint_as_float(f2tf(v.x));
    v.y = __uint_as_float(f2tf(v.y));
    v.z = __uint_as_float(f2tf(v.z));
    v.w = __uint_as_float(f2tf(v.w));
    dst[i] = v;
}

// ======================= elementwise kernels =======================
__device__ __forceinline__ float sigm(float x) { return 1.0f / (1.0f + expf(-x)); }

__global__ void gates_kernel(const float* __restrict__ h_re, const float* __restrict__ h_im,
                             const float2* __restrict__ px, const float2* __restrict__ pzr,
                             float2* __restrict__ zout,
                             float* __restrict__ rh_re, float* __restrict__ rh_im)
{
    long long i = blockIdx.x * (long long)blockDim.x + threadIdx.x;
    if (i >= BH) return;
    float2 p0 = px[i], p1 = px[BH + i];
    float2 q0 = pzr[i], q1 = pzr[BH + i];
    float zr = sigm(p0.x + q0.x), zi = sigm(p0.y + q0.y);
    float rr = sigm(p1.x + q1.x), ri = sigm(p1.y + q1.y);
    float hr = h_re[i], hi = h_im[i];
    zout[i]  = make_float2(zr, zi);
    // r*h, pre-rounded to tf32 for GEMM3
    rh_re[i] = __uint_as_float(f2tf(rr * hr - ri * hi));
    rh_im[i] = __uint_as_float(f2tf(rr * hi + ri * hr));
}

__global__ void final_kernel(const float* __restrict__ h_re, const float* __restrict__ h_im,
                             const float2* __restrict__ px2, const float2* __restrict__ ph,
                             const float2* __restrict__ zin, float2* __restrict__ out)
{
    long long i = blockIdx.x * (long long)blockDim.x + threadIdx.x;
    if (i >= BH) return;
    float2 p = px2[i], q = ph[i];
    float tr = p.x + q.x, ti = p.y + q.y;
    float mag = sqrtf(tr * tr + ti * ti);
    float s = (mag > 0.0f) ? (tanhf(mag) / mag) : 1.0f;
    float htr = s * tr, hti = s * ti;
    float2 z = zin[i];
    float hr = h_re[i], hi = h_im[i];
    float or_ = 1.0f - z.x, oi = -z.y;
    float hnr = or_ * hr - oi * hi + z.x * htr - z.y * hti;
    float hni = or_ * hi + oi * hr + z.x * hti + z.y * htr;
    out[i] = make_float2(hnr, hni);
}

// ======================= launch =======================
extern "C" void kernel_launch(void* const* d_in, const int* in_sizes, int n_in,
                              void* d_out, int out_size)
{
    const float* x_re  = (const float*)d_in[0];
    const float* x_im  = (const float*)d_in[1];
    const float* h_re  = (const float*)d_in[2];
    const float* h_im  = (const float*)d_in[3];
    const float* Wx_re = (const float*)d_in[4];
    const float* Wx_im = (const float*)d_in[5];
    const float* Wh_re = (const float*)d_in[6];
    const float* Wh_im = (const float*)d_in[7];
    const float* bx_re = (const float*)d_in[8];
    const float* bx_im = (const float*)d_in[9];
    const float* bh_re = (const float*)d_in[10];
    const float* bh_im = (const float*)d_in[11];

    float2* px;   cudaGetSymbolAddress((void**)&px,   g_px);
    float2* pzr;  cudaGetSymbolAddress((void**)&pzr,  g_pzr);
    float2* zbuf; cudaGetSymbolAddress((void**)&zbuf, g_z);
    float2* ph;   cudaGetSymbolAddress((void**)&ph,   g_ph);
    float*  rhre; cudaGetSymbolAddress((void**)&rhre, g_rh_re);
    float*  rhim; cudaGetSymbolAddress((void**)&rhim, g_rh_im);
    float *txr, *txi, *thr, *thi, *wxr, *wxi, *whr, *whi;
    cudaGetSymbolAddress((void**)&txr, g_tx_re);
    cudaGetSymbolAddress((void**)&txi, g_tx_im);
    cudaGetSymbolAddress((void**)&thr, g_th_re);
    cudaGetSymbolAddress((void**)&thi, g_th_im);
    cudaGetSymbolAddress((void**)&wxr, g_tWx_re);
    cudaGetSymbolAddress((void**)&wxi, g_tWx_im);
    cudaGetSymbolAddress((void**)&whr, g_tWh_re);
    cudaGetSymbolAddress((void**)&whi, g_tWh_im);

    cudaFuncSetAttribute(cgemm_tc, cudaFuncAttributeMaxDynamicSharedMemorySize, SMEM_DYN);

    const int nBH4 = (int)(BH / 4);
    const int nW4  = WSZ / 4;
    dim3 rblk(256);
    // prep: round inputs to tf32 once
    round_tf32_kernel<<<(nBH4 + 255) / 256, rblk>>>((const float4*)x_re, (float4*)txr, nBH4);
    round_tf32_kernel<<<(nBH4 + 255) / 256, rblk>>>((const float4*)x_im, (float4*)txi, nBH4);
    round_tf32_kernel<<<(nBH4 + 255) / 256, rblk>>>((const float4*)h_re, (float4*)thr, nBH4);
    round_tf32_kernel<<<(nBH4 + 255) / 256, rblk>>>((const float4*)h_im, (float4*)thi, nBH4);
    round_tf32_kernel<<<(nW4 + 255) / 256, rblk>>>((const float4*)Wx_re, (float4*)wxr, nW4);
    round_tf32_kernel<<<(nW4 + 255) / 256, rblk>>>((const float4*)Wx_im, (float4*)wxi, nW4);
    round_tf32_kernel<<<(nW4 + 255) / 256, rblk>>>((const float4*)Wh_re, (float4*)whr, nW4);
    round_tf32_kernel<<<(nW4 + 255) / 256, rblk>>>((const float4*)Wh_im, (float4*)whi, nW4);

    dim3 blk(512);
    dim3 grid_px(Hd / 128, Bsz / 128, 3);
    dim3 grid_zr(Hd / 128, Bsz / 128, 2);
    dim3 grid_h (Hd / 128, Bsz / 128, 1);
    dim3 eblk(256);
    dim3 egrid((unsigned)(BH / 256));

    cgemm_tc<<<grid_px, blk, SMEM_DYN>>>(txr, txi, wxr, wxi, bx_re, bx_im, px, BH);
    cgemm_tc<<<grid_zr, blk, SMEM_DYN>>>(thr, thi, whr, whi, bh_re, bh_im, pzr, BH);
    gates_kernel<<<egrid, eblk>>>(h_re, h_im, px, pzr, zbuf, rhre, rhim);
    cgemm_tc<<<grid_h, blk, SMEM_DYN>>>(rhre, rhim,
                                        whr + 2ull * Hd * Hd, whi + 2ull * Hd * Hd,
                                        bh_re + 2 * Hd, bh_im + 2 * Hd, ph, BH);
    final_kernel<<<egrid, eblk>>>(h_re, h_im, px + 2 * BH, ph, zbuf, (float2*)d_out);
}

// round 10
// speedup vs baseline: 4.0127x; 1.0313x over previous
#include <cuda_runtime.h>
#include <cstdint>
#include <math.h>

static constexpr int Bsz = 16384;
static constexpr int Hd  = 512;
static constexpr long long BH = (long long)Bsz * Hd;   // 8388608
static constexpr int WSZ = 3 * Hd * Hd;

// -------- scratch (device globals; allocation-free rule) --------
__device__ float2 g_px [3ull * Bsz * Hd];
__device__ float2 g_z  [(unsigned long long)Bsz * Hd];
__device__ float  g_rh_re[(unsigned long long)Bsz * Hd];
__device__ float  g_rh_im[(unsigned long long)Bsz * Hd];
// tf32-rounded copies
__device__ float  g_tx_re[(unsigned long long)Bsz * Hd];
__device__ float  g_tx_im[(unsigned long long)Bsz * Hd];
__device__ float  g_th_re[(unsigned long long)Bsz * Hd];
__device__ float  g_th_im[(unsigned long long)Bsz * Hd];
__device__ float  g_tWx_re[WSZ];
__device__ float  g_tWx_im[WSZ];
__device__ float  g_tWh_re[WSZ];
__device__ float  g_tWh_im[WSZ];

// ======================= PTX helpers (base-target only) =======================
__device__ __forceinline__ uint32_t smem_u32(const void* p){
    uint32_t a;
    asm("{ .reg .u64 t; cvta.to.shared.u64 t, %1; cvt.u32.u64 %0, t; }" : "=r"(a) : "l"(p));
    return a;
}
__device__ __forceinline__ void cp16(uint32_t dst, const void* src){
    asm volatile("cp.async.cg.shared.global [%0], [%1], 16;" :: "r"(dst), "l"(src));
}
#define CP_COMMIT() asm volatile("cp.async.commit_group;" ::: "memory")
#define CP_WAIT(n)  asm volatile("cp.async.wait_group %0;" :: "n"(n) : "memory")

__device__ __forceinline__ uint32_t f2tf(float x){
    uint32_t r; asm("cvt.rna.tf32.f32 %0, %1;" : "=r"(r) : "f"(x)); return r;
}
__device__ __forceinline__ void ldsm4(uint32_t* r, uint32_t addr){
    asm volatile("ldmatrix.sync.aligned.m8n8.x4.shared.b16 {%0,%1,%2,%3}, [%4];"
        : "=r"(r[0]), "=r"(r[1]), "=r"(r[2]), "=r"(r[3]) : "r"(addr));
}
__device__ __forceinline__ void mma8(float* c, const uint32_t* a, uint32_t b0, uint32_t b1){
    asm volatile(
        "mma.sync.aligned.m16n8k8.row.col.f32.tf32.tf32.f32 "
        "{%0,%1,%2,%3}, {%4,%5,%6,%7}, {%8,%9}, {%0,%1,%2,%3};"
        : "+f"(c[0]), "+f"(c[1]), "+f"(c[2]), "+f"(c[3])
        : "r"(a[0]), "r"(a[1]), "r"(a[2]), "r"(a[3]), "r"(b0), "r"(b1));
}
__device__ __forceinline__ float sigm(float x) { return 1.0f / (1.0f + expf(-x)); }

// ======================= tensor-core complex GEMM (mma.sync tf32) ============
// Inputs PRE-ROUNDED to tf32. CTA tile 128x128, 16 warps of 32x32, K chunks of 32.
// 3-stage cp.async pipeline, one __syncthreads per chunk, ldmatrix fragment feed.
static constexpr int KT = 32;
static constexpr int NIT = Hd / KT;              // 16
static constexpr int RS = 36;                    // padded row stride (floats)
static constexpr int OArB = 0;                   // byte plane offsets
static constexpr int OAiB = 128 * RS * 4;
static constexpr int OWrB = 256 * RS * 4;
static constexpr int OWiB = 384 * RS * 4;
static constexpr int STG_B = 512 * RS * 4;       // 73728 bytes/stage
static constexpr int SMEM_DYN = 3 * STG_B;       // 221184

// MODE 0: C = px (bias store).  MODE 1: g0 -> z gate, g1 -> r*h planes.
// MODE 2: final output (polar tanh + gate mix).
template<int MODE>
__global__ __launch_bounds__(512)
void cgemm_tc(const float* __restrict__ A_re, const float* __restrict__ A_im,
              const float* __restrict__ W_re, const float* __restrict__ W_im,
              const float* __restrict__ b_re, const float* __restrict__ b_im,
              float2* __restrict__ outC, const float2* __restrict__ pxb,
              const float* __restrict__ hre, const float* __restrict__ him,
              const float2* __restrict__ zin, float2* __restrict__ zout,
              float* __restrict__ rhre, float* __restrict__ rhim)
{
    extern __shared__ __align__(16) float smf[];
    const int tid = threadIdx.x;
    const int w   = tid >> 5, l = tid & 31;
    const int gid = l >> 2, tig = l & 3;
    const int wm  = w & 3;
    const int wn  = w >> 2;
    const int g   = blockIdx.z;
    const int mb  = blockIdx.y * 128;
    const int nb  = blockIdx.x * 128;
    const uint32_t smb = smem_u32(smf);

    const char* Wr = (const char*)(W_re + (size_t)g * Hd * Hd);
    const char* Wi = (const char*)(W_im + (size_t)g * Hd * Hd);
    const char* Ar = (const char*)A_re;
    const char* Ai = (const char*)A_im;

    // ldmatrix per-thread tile-row offsets (bytes within plane), +k0*4 per slice
    const int l7 = l & 7, l8 = (l >> 3) & 1, l16 = (l >> 4) & 1;
    uint32_t aoff[2], boff[2];
#pragma unroll
    for (int mi = 0; mi < 2; mi++)
        aoff[mi] = (uint32_t)(((wm * 32 + mi * 16 + l8 * 8 + l7) * RS + l16 * 4) * 4);
#pragma unroll
    for (int P = 0; P < 2; P++)
        boff[P] = (uint32_t)(((wn * 32 + P * 16 + l16 * 8 + l7) * RS + l8 * 4) * 4);

    auto load_stage = [&](int kb, int st){
        const uint32_t base = smb + st * STG_B;
        const size_t kby = (size_t)kb * (KT * 4);
#pragma unroll
        for (int i = 0; i < 8; i++){
            int c   = i * 512 + tid;
            int row = c >> 3;
            int j   = (c & 7) * 16;
            if (row < 128){
                cp16(base + OArB + (row * RS) * 4 + j, Ar + (size_t)(mb + row) * 2048 + kby + j);
            } else if (row < 256){
                int r = row - 128;
                cp16(base + OAiB + (r * RS) * 4 + j,   Ai + (size_t)(mb + r) * 2048 + kby + j);
            } else if (row < 384){
                int r = row - 256;
                cp16(base + OWrB + (r * RS) * 4 + j,   Wr + (size_t)(nb + r) * 2048 + kby + j);
            } else {
                int r = row - 384;
                cp16(base + OWiB + (r * RS) * 4 + j,   Wi + (size_t)(nb + r) * 2048 + kby + j);
            }
        }
    };

    float accRe[2][4][4], accIm[2][4][4];
#pragma unroll
    for (int mi = 0; mi < 2; mi++)
#pragma unroll
        for (int nj = 0; nj < 4; nj++)
#pragma unroll
            for (int q = 0; q < 4; q++){ accRe[mi][nj][q] = 0.f; accIm[mi][nj][q] = 0.f; }

    load_stage(0, 0); CP_COMMIT();
    load_stage(1, 1); CP_COMMIT();

    for (int kb = 0; kb < NIT; kb++){
        CP_WAIT(1);            // chunk kb resident (kb+1 may be in flight)
        __syncthreads();       // stage (kb+2)%3 fully consumed by all warps
        if (kb + 2 < NIT){
            load_stage(kb + 2, (kb + 2) % 3);
            CP_COMMIT();
        }

        const uint32_t stb = smb + (kb % 3) * STG_B;
#pragma unroll
        for (int kc = 0; kc < 4; kc++){
            const uint32_t k0b = kc * 32;   // 8 floats
            uint32_t fAr[2][4], fAi[2][4], bWr[2][4], bWi[2][4];
            ldsm4(fAr[0], stb + OArB + aoff[0] + k0b);
            ldsm4(fAr[1], stb + OArB + aoff[1] + k0b);
            ldsm4(fAi[0], stb + OAiB + aoff[0] + k0b);
            ldsm4(fAi[1], stb + OAiB + aoff[1] + k0b);
            ldsm4(bWr[0], stb + OWrB + boff[0] + k0b);
            ldsm4(bWr[1], stb + OWrB + boff[1] + k0b);
            ldsm4(bWi[0], stb + OWiB + boff[0] + k0b);
            ldsm4(bWi[1], stb + OWiB + boff[1] + k0b);
#pragma unroll
            for (int nj = 0; nj < 4; nj++){
                uint32_t br0 = bWr[nj >> 1][(nj & 1) * 2];
                uint32_t br1 = bWr[nj >> 1][(nj & 1) * 2 + 1];
                uint32_t bi0 = bWi[nj >> 1][(nj & 1) * 2];
                uint32_t bi1 = bWi[nj >> 1][(nj & 1) * 2 + 1];
                uint32_t bn0 = bi0 ^ 0x80000000u;
                uint32_t bn1 = bi1 ^ 0x80000000u;
#pragma unroll
                for (int mi = 0; mi < 2; mi++){
                    mma8(accRe[mi][nj], fAr[mi], br0, br1);
                    mma8(accRe[mi][nj], fAi[mi], bn0, bn1);
                    mma8(accIm[mi][nj], fAr[mi], bi0, bi1);
                    mma8(accIm[mi][nj], fAi[mi], br0, br1);
                }
            }
        }
    }

    // ======================= fused epilogues =======================
    const float* brp = b_re + (size_t)g * Hd;
    const float* bip = b_im + (size_t)g * Hd;

#pragma unroll
    for (int nj = 0; nj < 4; nj++){
        const int n = nb + wn * 32 + nj * 8 + tig * 2;
        const float br0 = brp[n],     bi0 = bip[n];
        const float br1 = brp[n + 1], bi1 = bip[n + 1];
#pragma unroll
        for (int mi = 0; mi < 2; mi++){
#pragma unroll
            for (int half = 0; half < 2; half++){
                const int row = mb + wm * 32 + mi * 16 + gid + half * 8;
                const size_t idx = (size_t)row * Hd + n;
                const float pr0 = accRe[mi][nj][half * 2]     + br0;
                const float pi0 = accIm[mi][nj][half * 2]     + bi0;
                const float pr1 = accRe[mi][nj][half * 2 + 1] + br1;
                const float pi1 = accIm[mi][nj][half * 2 + 1] + bi1;

                if (MODE == 0){
                    float2* Cg = outC + (size_t)g * BH;
                    *(float4*)&Cg[idx] = make_float4(pr0, pi0, pr1, pi1);
                }
                else if (MODE == 1){
                    const float2* pxg = pxb + (size_t)g * BH;
                    float4 pv = *(const float4*)&pxg[idx];
                    float v0r = sigm(pv.x + pr0), v0i = sigm(pv.y + pi0);
                    float v1r = sigm(pv.z + pr1), v1i = sigm(pv.w + pi1);
                    if (g == 0){
                        *(float4*)&zout[idx] = make_float4(v0r, v0i, v1r, v1i);
                    } else {
                        float2 hr = *(const float2*)&hre[idx];
                        float2 hi = *(const float2*)&him[idx];
                        float2 rr = make_float2(
                            __uint_as_float(f2tf(v0r * hr.x - v0i * hi.x)),
                            __uint_as_float(f2tf(v1r * hr.y - v1i * hi.y)));
                        float2 ri = make_float2(
                            __uint_as_float(f2tf(v0r * hi.x + v0i * hr.x)),
                            __uint_as_float(f2tf(v1r * hi.y + v1i * hr.y)));
                        *(float2*)&rhre[idx] = rr;
                        *(float2*)&rhim[idx] = ri;
                    }
                }
                else {  // MODE 2: final
                    float4 pv = *(const float4*)&pxb[idx];
                    float4 zv = *(const float4*)&zin[idx];
                    float2 hr = *(const float2*)&hre[idx];
                    float2 hi = *(const float2*)&him[idx];
                    float4 ov;
                    {
                        float tr = pv.x + pr0, ti = pv.y + pi0;
                        float mag = sqrtf(tr * tr + ti * ti);
                        float s = (mag > 0.f) ? (tanhf(mag) / mag) : 1.f;
                        float htr = s * tr, hti = s * ti;
                        float or_ = 1.f - zv.x, oi = -zv.y;
                        ov.x = or_ * hr.x - oi * hi.x + zv.x * htr - zv.y * hti;
                        ov.y = or_ * hi.x + oi * hr.x + zv.x * hti + zv.y * htr;
                    }
                    {
                        float tr = pv.z + pr1, ti = pv.w + pi1;
                        float mag = sqrtf(tr * tr + ti * ti);
                        float s = (mag > 0.f) ? (tanhf(mag) / mag) : 1.f;
                        float htr = s * tr, hti = s * ti;
                        float or_ = 1.f - zv.z, oi = -zv.w;
                        ov.z = or_ * hr.y - oi * hi.y + zv.z * htr - zv.w * hti;
                        ov.w = or_ * hi.y + oi * hr.y + zv.z * hti + zv.w * htr;
                    }
                    *(float4*)&outC[idx] = ov;
                }
            }
        }
    }
}

// ======================= prep: tf32 rounding pass =======================
__global__ void round_tf32_kernel(const float4* __restrict__ src, float4* __restrict__ dst, int n4)
{
    int i = blockIdx.x * blockDim.x + threadIdx.x;
    if (i >= n4) return;
    float4 v = src[i];
    v.x = __uint_as_float(f2tf(v.x));
    v.y = __uint_as_float(f2tf(v.y));
    v.z = __uint_as_float(f2tf(v.z));
    v.w = __uint_as_float(f2tf(v.w));
    dst[i] = v;
}

// ======================= launch =======================
extern "C" void kernel_launch(void* const* d_in, const int* in_sizes, int n_in,
                              void* d_out, int out_size)
{
    const float* x_re  = (const float*)d_in[0];
    const float* x_im  = (const float*)d_in[1];
    const float* h_re  = (const float*)d_in[2];
    const float* h_im  = (const float*)d_in[3];
    const float* Wx_re = (const float*)d_in[4];
    const float* Wx_im = (const float*)d_in[5];
    const float* Wh_re = (const float*)d_in[6];
    const float* Wh_im = (const float*)d_in[7];
    const float* bx_re = (const float*)d_in[8];
    const float* bx_im = (const float*)d_in[9];
    const float* bh_re = (const float*)d_in[10];
    const float* bh_im = (const float*)d_in[11];

    float2* px;   cudaGetSymbolAddress((void**)&px,   g_px);
    float2* zbuf; cudaGetSymbolAddress((void**)&zbuf, g_z);
    float*  rhre; cudaGetSymbolAddress((void**)&rhre, g_rh_re);
    float*  rhim; cudaGetSymbolAddress((void**)&rhim, g_rh_im);
    float *txr, *txi, *thr, *thi, *wxr, *wxi, *whr, *whi;
    cudaGetSymbolAddress((void**)&txr, g_tx_re);
    cudaGetSymbolAddress((void**)&txi, g_tx_im);
    cudaGetSymbolAddress((void**)&thr, g_th_re);
    cudaGetSymbolAddress((void**)&thi, g_th_im);
    cudaGetSymbolAddress((void**)&wxr, g_tWx_re);
    cudaGetSymbolAddress((void**)&wxi, g_tWx_im);
    cudaGetSymbolAddress((void**)&whr, g_tWh_re);
    cudaGetSymbolAddress((void**)&whi, g_tWh_im);

    cudaFuncSetAttribute(cgemm_tc<0>, cudaFuncAttributeMaxDynamicSharedMemorySize, SMEM_DYN);
    cudaFuncSetAttribute(cgemm_tc<1>, cudaFuncAttributeMaxDynamicSharedMemorySize, SMEM_DYN);
    cudaFuncSetAttribute(cgemm_tc<2>, cudaFuncAttributeMaxDynamicSharedMemorySize, SMEM_DYN);

    const int nBH4 = (int)(BH / 4);
    const int nW4  = WSZ / 4;
    dim3 rblk(256);
    round_tf32_kernel<<<(nBH4 + 255) / 256, rblk>>>((const float4*)x_re, (float4*)txr, nBH4);
    round_tf32_kernel<<<(nBH4 + 255) / 256, rblk>>>((const float4*)x_im, (float4*)txi, nBH4);
    round_tf32_kernel<<<(nBH4 + 255) / 256, rblk>>>((const float4*)h_re, (float4*)thr, nBH4);
    round_tf32_kernel<<<(nBH4 + 255) / 256, rblk>>>((const float4*)h_im, (float4*)thi, nBH4);
    round_tf32_kernel<<<(nW4 + 255) / 256, rblk>>>((const float4*)Wx_re, (float4*)wxr, nW4);
    round_tf32_kernel<<<(nW4 + 255) / 256, rblk>>>((const float4*)Wx_im, (float4*)wxi, nW4);
    round_tf32_kernel<<<(nW4 + 255) / 256, rblk>>>((const float4*)Wh_re, (float4*)whr, nW4);
    round_tf32_kernel<<<(nW4 + 255) / 256, rblk>>>((const float4*)Wh_im, (float4*)whi, nW4);

    dim3 blk(512);
    dim3 grid_px(Hd / 128, Bsz / 128, 3);
    dim3 grid_zr(Hd / 128, Bsz / 128, 2);
    dim3 grid_h (Hd / 128, Bsz / 128, 1);

    // 1) px[k] = x @ Wx[k]^T + bx[k]
    cgemm_tc<0><<<grid_px, blk, SMEM_DYN>>>(txr, txi, wxr, wxi, bx_re, bx_im,
                                            px, nullptr, nullptr, nullptr,
                                            nullptr, nullptr, nullptr, nullptr);
    // 2) z (g=0) and r*h (g=1), fused epilogue
    cgemm_tc<1><<<grid_zr, blk, SMEM_DYN>>>(thr, thi, whr, whi, bh_re, bh_im,
                                            nullptr, px, h_re, h_im,
                                            nullptr, zbuf, rhre, rhim);
    // 3) final: ph -> h_tilde -> h_new, fused epilogue
    cgemm_tc<2><<<grid_h, blk, SMEM_DYN>>>(rhre, rhim,
                                           whr + 2ull * Hd * Hd, whi + 2ull * Hd * Hd,
                                           bh_re + 2 * Hd, bh_im + 2 * Hd,
                                           (float2*)d_out, px + 2 * BH, h_re, h_im,
                                           zbuf, nullptr, nullptr, nullptr);
}

// round 12
// speedup vs baseline: 5.5120x; 1.3736x over previous
#include <cuda_runtime.h>
#include <cuda_fp16.h>
#include <cstdint>
#include <math.h>

static constexpr int Bsz = 16384;
static constexpr int Hd  = 512;
static constexpr long long BH = (long long)Bsz * Hd;   // 8388608
static constexpr int WSZ = 3 * Hd * Hd;

// -------- scratch (device globals; allocation-free rule) --------
__device__ float2 g_px [3ull * Bsz * Hd];
__device__ float2 g_z  [(unsigned long long)Bsz * Hd];
__device__ __half g_rh_re[(unsigned long long)Bsz * Hd];
__device__ __half g_rh_im[(unsigned long long)Bsz * Hd];
// fp16-rounded copies
__device__ __half g_tx_re[(unsigned long long)Bsz * Hd];
__device__ __half g_tx_im[(unsigned long long)Bsz * Hd];
__device__ __half g_th_re[(unsigned long long)Bsz * Hd];
__device__ __half g_th_im[(unsigned long long)Bsz * Hd];
__device__ __half g_tWx_re[WSZ];
__device__ __half g_tWx_im[WSZ];
__device__ __half g_tWh_re[WSZ];
__device__ __half g_tWh_im[WSZ];

// ======================= PTX helpers (base-target only) =======================
__device__ __forceinline__ uint32_t smem_u32(const void* p){
    uint32_t a;
    asm("{ .reg .u64 t; cvta.to.shared.u64 t, %1; cvt.u32.u64 %0, t; }" : "=r"(a) : "l"(p));
    return a;
}
__device__ __forceinline__ void cp16(uint32_t dst, const void* src){
    asm volatile("cp.async.cg.shared.global [%0], [%1], 16;" :: "r"(dst), "l"(src));
}
#define CP_COMMIT() asm volatile("cp.async.commit_group;" ::: "memory")
#define CP_WAIT(n)  asm volatile("cp.async.wait_group %0;" :: "n"(n) : "memory")

__device__ __forceinline__ void ldsm4(uint32_t* r, uint32_t addr){
    asm volatile("ldmatrix.sync.aligned.m8n8.x4.shared.b16 {%0,%1,%2,%3}, [%4];"
        : "=r"(r[0]), "=r"(r[1]), "=r"(r[2]), "=r"(r[3]) : "r"(addr));
}
// fp16 MMA: D(f32) += A(m16k16 f16) * B(k16n8 f16)
__device__ __forceinline__ void mma16(float* c, const uint32_t* a, uint32_t b0, uint32_t b1){
    asm volatile(
        "mma.sync.aligned.m16n8k16.row.col.f32.f16.f16.f32 "
        "{%0,%1,%2,%3}, {%4,%5,%6,%7}, {%8,%9}, {%0,%1,%2,%3};"
        : "+f"(c[0]), "+f"(c[1]), "+f"(c[2]), "+f"(c[3])
        : "r"(a[0]), "r"(a[1]), "r"(a[2]), "r"(a[3]), "r"(b0), "r"(b1));
}
__device__ __forceinline__ float sigm(float x) { return 1.0f / (1.0f + expf(-x)); }

// ======================= fp16 tensor-core complex GEMM =======================
// C[g][m][n] = sum_k A[m][k]*W[g][n][k] + b[g][n]  (complex; fp16 split planes)
// CTA tile 128x128; 8 warps (2M x 4N) of 64x32 warp tiles; K chunks of 64 halves.
static constexpr int NIT  = 8;                   // 512 / 64
static constexpr int RSB  = 144;                 // row stride bytes (72 halves)
static constexpr int OArB = 0;
static constexpr int OAiB = 128 * RSB;           // 18432
static constexpr int OWrB = 256 * RSB;
static constexpr int OWiB = 384 * RSB;
static constexpr int STG_B = 512 * RSB;          // 73728
static constexpr int SMEM_DYN = 3 * STG_B;       // 221184

// MODE 0: store px. MODE 1: g0 -> z, g1 -> r*h (fp16 planes). MODE 2: final mix.
template<int MODE>
__global__ __launch_bounds__(256)
void cgemm_tc(const __half* __restrict__ A_re, const __half* __restrict__ A_im,
              const __half* __restrict__ W_re, const __half* __restrict__ W_im,
              const float* __restrict__ b_re, const float* __restrict__ b_im,
              float2* __restrict__ outC, const float2* __restrict__ pxb,
              const float* __restrict__ hre, const float* __restrict__ him,
              const float2* __restrict__ zin, float2* __restrict__ zout,
              __half* __restrict__ rhre, __half* __restrict__ rhim)
{
    extern __shared__ __align__(16) char smc[];
    const int tid = threadIdx.x;
    const int w   = tid >> 5, l = tid & 31;
    const int gid = l >> 2, tig = l & 3;
    const int wm  = w & 1;                       // 0..1 (M, 64 each)
    const int wn  = w >> 1;                      // 0..3 (N, 32 each)
    const int g   = blockIdx.z;
    const int mb  = blockIdx.y * 128;
    const int nb  = blockIdx.x * 128;
    const uint32_t smb = smem_u32(smc);

    const char* Wr = (const char*)(W_re + (size_t)g * Hd * Hd);
    const char* Wi = (const char*)(W_im + (size_t)g * Hd * Hd);
    const char* Ar = (const char*)A_re;
    const char* Ai = (const char*)A_im;

    // ldmatrix per-thread byte offsets within a plane (tile rows + k8-group col)
    const int l7 = l & 7, l8 = (l >> 3) & 1, l16 = (l >> 4) & 1;
    uint32_t aoff[4], boff[2];
#pragma unroll
    for (int mi = 0; mi < 4; mi++)
        aoff[mi] = (uint32_t)((wm * 64 + mi * 16 + l8 * 8 + l7) * RSB + l16 * 16);
#pragma unroll
    for (int P = 0; P < 2; P++)
        boff[P] = (uint32_t)((wn * 32 + P * 16 + l8 * 8 + l7) * RSB + l16 * 16);

    // loader: 512 rows x 8 x 16B = 4096 cp16, 16 per thread. Row data = 128B.
    auto load_stage = [&](int kb, int st){
        const uint32_t base = smb + st * STG_B;
        const size_t kby = (size_t)kb * 128;     // 64 halves
#pragma unroll
        for (int i = 0; i < 16; i++){
            int c   = i * 256 + tid;
            int row = c >> 3;
            int j   = (c & 7) * 16;
            if (row < 128){
                cp16(base + OArB + row * RSB + j, Ar + (size_t)(mb + row) * 1024 + kby + j);
            } else if (row < 256){
                int r = row - 128;
                cp16(base + OAiB + r * RSB + j,   Ai + (size_t)(mb + r) * 1024 + kby + j);
            } else if (row < 384){
                int r = row - 256;
                cp16(base + OWrB + r * RSB + j,   Wr + (size_t)(nb + r) * 1024 + kby + j);
            } else {
                int r = row - 384;
                cp16(base + OWiB + r * RSB + j,   Wi + (size_t)(nb + r) * 1024 + kby + j);
            }
        }
    };

    float accRe[4][4][4], accIm[4][4][4];
#pragma unroll
    for (int mi = 0; mi < 4; mi++)
#pragma unroll
        for (int nj = 0; nj < 4; nj++)
#pragma unroll
            for (int q = 0; q < 4; q++){ accRe[mi][nj][q] = 0.f; accIm[mi][nj][q] = 0.f; }

    load_stage(0, 0); CP_COMMIT();
    load_stage(1, 1); CP_COMMIT();

    for (int kb = 0; kb < NIT; kb++){
        CP_WAIT(1);
        __syncthreads();
        if (kb + 2 < NIT){
            load_stage(kb + 2, (kb + 2) % 3);
            CP_COMMIT();
        }

        const uint32_t stb = smb + (kb % 3) * STG_B;
#pragma unroll
        for (int kc = 0; kc < 4; kc++){
            const uint32_t k0b = kc * 32;        // 16 halves
            uint32_t fAr[4][4], fAi[4][4], bWr[2][4], bWi[2][4];
            ldsm4(bWr[0], stb + OWrB + boff[0] + k0b);
            ldsm4(bWr[1], stb + OWrB + boff[1] + k0b);
            ldsm4(bWi[0], stb + OWiB + boff[0] + k0b);
            ldsm4(bWi[1], stb + OWiB + boff[1] + k0b);
#pragma unroll
            for (int mi = 0; mi < 4; mi++){
                ldsm4(fAr[mi], stb + OArB + aoff[mi] + k0b);
                ldsm4(fAi[mi], stb + OAiB + aoff[mi] + k0b);
            }
#pragma unroll
            for (int nj = 0; nj < 4; nj++){
                const int P = nj >> 1, q = nj & 1;
                uint32_t br0 = bWr[P][q],     br1 = bWr[P][q + 2];
                uint32_t bi0 = bWi[P][q],     bi1 = bWi[P][q + 2];
                uint32_t bn0 = bi0 ^ 0x80008000u;   // -wi (fp16x2 sign flip)
                uint32_t bn1 = bi1 ^ 0x80008000u;
#pragma unroll
                for (int mi = 0; mi < 4; mi++){
                    mma16(accRe[mi][nj], fAr[mi], br0, br1);
                    mma16(accRe[mi][nj], fAi[mi], bn0, bn1);
                    mma16(accIm[mi][nj], fAr[mi], bi0, bi1);
                    mma16(accIm[mi][nj], fAi[mi], br0, br1);
                }
            }
        }
    }

    // ======================= fused epilogues =======================
    const float* brp = b_re + (size_t)g * Hd;
    const float* bip = b_im + (size_t)g * Hd;

#pragma unroll
    for (int nj = 0; nj < 4; nj++){
        const int n = nb + wn * 32 + nj * 8 + tig * 2;
        const float br0 = brp[n],     bi0 = bip[n];
        const float br1 = brp[n + 1], bi1 = bip[n + 1];
#pragma unroll
        for (int mi = 0; mi < 4; mi++){
#pragma unroll
            for (int half = 0; half < 2; half++){
                const int row = mb + wm * 64 + mi * 16 + gid + half * 8;
                const size_t idx = (size_t)row * Hd + n;
                const float pr0 = accRe[mi][nj][half * 2]     + br0;
                const float pi0 = accIm[mi][nj][half * 2]     + bi0;
                const float pr1 = accRe[mi][nj][half * 2 + 1] + br1;
                const float pi1 = accIm[mi][nj][half * 2 + 1] + bi1;

                if (MODE == 0){
                    float2* Cg = outC + (size_t)g * BH;
                    *(float4*)&Cg[idx] = make_float4(pr0, pi0, pr1, pi1);
                }
                else if (MODE == 1){
                    const float2* pxg = pxb + (size_t)g * BH;
                    float4 pv = *(const float4*)&pxg[idx];
                    float v0r = sigm(pv.x + pr0), v0i = sigm(pv.y + pi0);
                    float v1r = sigm(pv.z + pr1), v1i = sigm(pv.w + pi1);
                    if (g == 0){
                        *(float4*)&zout[idx] = make_float4(v0r, v0i, v1r, v1i);
                    } else {
                        float2 hr = *(const float2*)&hre[idx];
                        float2 hi = *(const float2*)&him[idx];
                        __half2 rr = __floats2half2_rn(v0r * hr.x - v0i * hi.x,
                                                       v1r * hr.y - v1i * hi.y);
                        __half2 ri = __floats2half2_rn(v0r * hi.x + v0i * hr.x,
                                                       v1r * hi.y + v1i * hr.y);
                        *(__half2*)&rhre[idx] = rr;
                        *(__half2*)&rhim[idx] = ri;
                    }
                }
                else {  // MODE 2
                    float4 pv = *(const float4*)&pxb[idx];
                    float4 zv = *(const float4*)&zin[idx];
                    float2 hr = *(const float2*)&hre[idx];
                    float2 hi = *(const float2*)&him[idx];
                    float4 ov;
                    {
                        float tr = pv.x + pr0, ti = pv.y + pi0;
                        float mag = sqrtf(tr * tr + ti * ti);
                        float s = (mag > 0.f) ? (tanhf(mag) / mag) : 1.f;
                        float htr = s * tr, hti = s * ti;
                        float or_ = 1.f - zv.x, oi = -zv.y;
                        ov.x = or_ * hr.x - oi * hi.x + zv.x * htr - zv.y * hti;
                        ov.y = or_ * hi.x + oi * hr.x + zv.x * hti + zv.y * htr;
                    }
                    {
                        float tr = pv.z + pr1, ti = pv.w + pi1;
                        float mag = sqrtf(tr * tr + ti * ti);
                        float s = (mag > 0.f) ? (tanhf(mag) / mag) : 1.f;
                        float htr = s * tr, hti = s * ti;
                        float or_ = 1.f - zv.z, oi = -zv.w;
                        ov.z = or_ * hr.y - oi * hi.y + zv.z * htr - zv.w * hti;
                        ov.w = or_ * hi.y + oi * hr.y + zv.z * hti + zv.w * htr;
                    }
                    *(float4*)&outC[idx] = ov;
                }
            }
        }
    }
}

// ======================= prep: fp32 -> fp16 plane conversion ==================
__global__ void to_fp16_kernel(const float4* __restrict__ src, __half2* __restrict__ dst, int n4)
{
    int i = blockIdx.x * blockDim.x + threadIdx.x;
    if (i >= n4) return;
    float4 v = src[i];
    dst[i * 2]     = __floats2half2_rn(v.x, v.y);
    dst[i * 2 + 1] = __floats2half2_rn(v.z, v.w);
}

// ======================= launch =======================
extern "C" void kernel_launch(void* const* d_in, const int* in_sizes, int n_in,
                              void* d_out, int out_size)
{
    const float* x_re  = (const float*)d_in[0];
    const float* x_im  = (const float*)d_in[1];
    const float* h_re  = (const float*)d_in[2];
    const float* h_im  = (const float*)d_in[3];
    const float* Wx_re = (const float*)d_in[4];
    const float* Wx_im = (const float*)d_in[5];
    const float* Wh_re = (const float*)d_in[6];
    const float* Wh_im = (const float*)d_in[7];
    const float* bx_re = (const float*)d_in[8];
    const float* bx_im = (const float*)d_in[9];
    const float* bh_re = (const float*)d_in[10];
    const float* bh_im = (const float*)d_in[11];

    float2* px;   cudaGetSymbolAddress((void**)&px,   g_px);
    float2* zbuf; cudaGetSymbolAddress((void**)&zbuf, g_z);
    __half *rhre, *rhim, *txr, *txi, *thr, *thi, *wxr, *wxi, *whr, *whi;
    cudaGetSymbolAddress((void**)&rhre, g_rh_re);
    cudaGetSymbolAddress((void**)&rhim, g_rh_im);
    cudaGetSymbolAddress((void**)&txr, g_tx_re);
    cudaGetSymbolAddress((void**)&txi, g_tx_im);
    cudaGetSymbolAddress((void**)&thr, g_th_re);
    cudaGetSymbolAddress((void**)&thi, g_th_im);
    cudaGetSymbolAddress((void**)&wxr, g_tWx_re);
    cudaGetSymbolAddress((void**)&wxi, g_tWx_im);
    cudaGetSymbolAddress((void**)&whr, g_tWh_re);
    cudaGetSymbolAddress((void**)&whi, g_tWh_im);

    cudaFuncSetAttribute(cgemm_tc<0>, cudaFuncAttributeMaxDynamicSharedMemorySize, SMEM_DYN);
    cudaFuncSetAttribute(cgemm_tc<1>, cudaFuncAttributeMaxDynamicSharedMemorySize, SMEM_DYN);
    cudaFuncSetAttribute(cgemm_tc<2>, cudaFuncAttributeMaxDynamicSharedMemorySize, SMEM_DYN);

    const int nBH4 = (int)(BH / 4);
    const int nW4  = WSZ / 4;
    dim3 rblk(256);
    to_fp16_kernel<<<(nBH4 + 255) / 256, rblk>>>((const float4*)x_re, (__half2*)txr, nBH4);
    to_fp16_kernel<<<(nBH4 + 255) / 256, rblk>>>((const float4*)x_im, (__half2*)txi, nBH4);
    to_fp16_kernel<<<(nBH4 + 255) / 256, rblk>>>((const float4*)h_re, (__half2*)thr, nBH4);
    to_fp16_kernel<<<(nBH4 + 255) / 256, rblk>>>((const float4*)h_im, (__half2*)thi, nBH4);
    to_fp16_kernel<<<(nW4 + 255) / 256, rblk>>>((const float4*)Wx_re, (__half2*)wxr, nW4);
    to_fp16_kernel<<<(nW4 + 255) / 256, rblk>>>((const float4*)Wx_im, (__half2*)wxi, nW4);
    to_fp16_kernel<<<(nW4 + 255) / 256, rblk>>>((const float4*)Wh_re, (__half2*)whr, nW4);
    to_fp16_kernel<<<(nW4 + 255) / 256, rblk>>>((const float4*)Wh_im, (__half2*)whi, nW4);

    dim3 blk(256);
    dim3 grid_px(Hd / 128, Bsz / 128, 3);
    dim3 grid_zr(Hd / 128, Bsz / 128, 2);
    dim3 grid_h (Hd / 128, Bsz / 128, 1);

    cgemm_tc<0><<<grid_px, blk, SMEM_DYN>>>(txr, txi, wxr, wxi, bx_re, bx_im,
                                            px, nullptr, nullptr, nullptr,
                                            nullptr, nullptr, nullptr, nullptr);
    cgemm_tc<1><<<grid_zr, blk, SMEM_DYN>>>(thr, thi, whr, whi, bh_re, bh_im,
                                            nullptr, px, h_re, h_im,
                                            nullptr, zbuf, rhre, rhim);
    cgemm_tc<2><<<grid_h, blk, SMEM_DYN>>>(rhre, rhim,
                                           whr + 2ull * Hd * Hd, whi + 2ull * Hd * Hd,
                                           bh_re + 2 * Hd, bh_im + 2 * Hd,
                                           (float2*)d_out, px + 2 * BH, h_re, h_im,
                                           zbuf, nullptr, nullptr, nullptr);
}

// round 13
// speedup vs baseline: 6.4623x; 1.1724x over previous
#include <cuda_runtime.h>
#include <cuda_fp16.h>
#include <cstdint>
#include <math.h>

static constexpr int Bsz = 16384;
static constexpr int Hd  = 512;
static constexpr long long BH = (long long)Bsz * Hd;   // 8388608
static constexpr int WSZ = 3 * Hd * Hd;

// -------- scratch (device globals; allocation-free rule) --------
__device__ float2 g_z  [(unsigned long long)Bsz * Hd];     // gate z (fp32 complex)
__device__ __half g_rh_re[(unsigned long long)Bsz * Hd];   // r*h planes (fp16)
__device__ __half g_rh_im[(unsigned long long)Bsz * Hd];
// fp16 copies of inputs
__device__ __half g_tx_re[(unsigned long long)Bsz * Hd];
__device__ __half g_tx_im[(unsigned long long)Bsz * Hd];
__device__ __half g_th_re[(unsigned long long)Bsz * Hd];
__device__ __half g_th_im[(unsigned long long)Bsz * Hd];
__device__ __half g_tWx_re[WSZ];
__device__ __half g_tWx_im[WSZ];
__device__ __half g_tWh_re[WSZ];
__device__ __half g_tWh_im[WSZ];

// ======================= PTX helpers (base-target only) =======================
__device__ __forceinline__ uint32_t smem_u32(const void* p){
    uint32_t a;
    asm("{ .reg .u64 t; cvta.to.shared.u64 t, %1; cvt.u32.u64 %0, t; }" : "=r"(a) : "l"(p));
    return a;
}
__device__ __forceinline__ void cp16(uint32_t dst, const void* src){
    asm volatile("cp.async.cg.shared.global [%0], [%1], 16;" :: "r"(dst), "l"(src));
}
#define CP_COMMIT() asm volatile("cp.async.commit_group;" ::: "memory")
#define CP_WAIT(n)  asm volatile("cp.async.wait_group %0;" :: "n"(n) : "memory")

__device__ __forceinline__ void ldsm4(uint32_t* r, uint32_t addr){
    asm volatile("ldmatrix.sync.aligned.m8n8.x4.shared.b16 {%0,%1,%2,%3}, [%4];"
        : "=r"(r[0]), "=r"(r[1]), "=r"(r[2]), "=r"(r[3]) : "r"(addr));
}
__device__ __forceinline__ void mma16(float* c, const uint32_t* a, uint32_t b0, uint32_t b1){
    asm volatile(
        "mma.sync.aligned.m16n8k16.row.col.f32.f16.f16.f32 "
        "{%0,%1,%2,%3}, {%4,%5,%6,%7}, {%8,%9}, {%0,%1,%2,%3};"
        : "+f"(c[0]), "+f"(c[1]), "+f"(c[2]), "+f"(c[3])
        : "r"(a[0]), "r"(a[1]), "r"(a[2]), "r"(a[3]), "r"(b0), "r"(b1));
}
__device__ __forceinline__ float sigm(float x) { return 1.0f / (1.0f + expf(-x)); }

// ======================= fused K=1024 complex GEMM ===========================
// acc[m][n] = sum_k A1[m][k]*W1[g][n][k] + A2[m][k]*W2[g][n][k]   (complex fp16)
// MODE 1: g=0 -> z = sigm(acc+b); g=1 -> r = sigm(acc+b), store r*h (fp16).
// MODE 2: final: h_tilde = polar_tanh(acc+b); out = (1-z)h + z*h_tilde.
static constexpr int NIT  = 16;                  // 1024 / 64
static constexpr int RSB  = 144;                 // row stride bytes (72 halves)
static constexpr int OArB = 0;
static constexpr int OAiB = 128 * RSB;
static constexpr int OWrB = 256 * RSB;
static constexpr int OWiB = 384 * RSB;
static constexpr int STG_B = 512 * RSB;          // 73728
static constexpr int SMEM_DYN = 3 * STG_B;       // 221184

template<int MODE>
__global__ __launch_bounds__(256)
void cgemm_fused(const __half* __restrict__ A1r, const __half* __restrict__ A1i,
                 const __half* __restrict__ A2r, const __half* __restrict__ A2i,
                 const __half* __restrict__ W1r, const __half* __restrict__ W1i,
                 const __half* __restrict__ W2r, const __half* __restrict__ W2i,
                 const float* __restrict__ b1r, const float* __restrict__ b1i,
                 const float* __restrict__ b2r, const float* __restrict__ b2i,
                 const float* __restrict__ hre, const float* __restrict__ him,
                 const float2* __restrict__ zin, float2* __restrict__ zout,
                 __half* __restrict__ rhre, __half* __restrict__ rhim,
                 float2* __restrict__ outC)
{
    extern __shared__ __align__(16) char smc[];
    const int tid = threadIdx.x;
    const int w   = tid >> 5, l = tid & 31;
    const int gid = l >> 2, tig = l & 3;
    const int wm  = w & 1;                       // 0..1 (M, 64 each)
    const int wn  = w >> 1;                      // 0..3 (N, 32 each)
    const int g   = blockIdx.z;
    const int mb  = blockIdx.y * 128;
    const int nb  = blockIdx.x * 128;
    const uint32_t smb = smem_u32(smc);

    const size_t gofs = (size_t)g * Hd * Hd;
    const char* pW1r = (const char*)(W1r + gofs);
    const char* pW1i = (const char*)(W1i + gofs);
    const char* pW2r = (const char*)(W2r + gofs);
    const char* pW2i = (const char*)(W2i + gofs);

    // ldmatrix per-thread byte offsets
    const int l7 = l & 7, l8 = (l >> 3) & 1, l16 = (l >> 4) & 1;
    uint32_t aoff[4], boff[2];
#pragma unroll
    for (int mi = 0; mi < 4; mi++)
        aoff[mi] = (uint32_t)((wm * 64 + mi * 16 + l8 * 8 + l7) * RSB + l16 * 16);
#pragma unroll
    for (int P = 0; P < 2; P++)
        boff[P] = (uint32_t)((wn * 32 + P * 16 + l8 * 8 + l7) * RSB + l16 * 16);

    // loader: segment 0 = (A1, W1) for kb<8, segment 1 = (A2, W2) for kb>=8
    auto load_stage = [&](int kb, int st){
        const uint32_t base = smb + st * STG_B;
        const bool s1 = (kb >= 8);
        const char* Ar = s1 ? (const char*)A2r : (const char*)A1r;
        const char* Ai = s1 ? (const char*)A2i : (const char*)A1i;
        const char* Wr = s1 ? pW2r : pW1r;
        const char* Wi = s1 ? pW2i : pW1i;
        const size_t kby = (size_t)(kb & 7) * 128;   // 64 halves
#pragma unroll
        for (int i = 0; i < 16; i++){
            int c   = i * 256 + tid;
            int row = c >> 3;
            int j   = (c & 7) * 16;
            if (row < 128){
                cp16(base + OArB + row * RSB + j, Ar + (size_t)(mb + row) * 1024 + kby + j);
            } else if (row < 256){
                int r = row - 128;
                cp16(base + OAiB + r * RSB + j,   Ai + (size_t)(mb + r) * 1024 + kby + j);
            } else if (row < 384){
                int r = row - 256;
                cp16(base + OWrB + r * RSB + j,   Wr + (size_t)(nb + r) * 1024 + kby + j);
            } else {
                int r = row - 384;
                cp16(base + OWiB + r * RSB + j,   Wi + (size_t)(nb + r) * 1024 + kby + j);
            }
        }
    };

    float accRe[4][4][4], accIm[4][4][4];
#pragma unroll
    for (int mi = 0; mi < 4; mi++)
#pragma unroll
        for (int nj = 0; nj < 4; nj++)
#pragma unroll
            for (int q = 0; q < 4; q++){ accRe[mi][nj][q] = 0.f; accIm[mi][nj][q] = 0.f; }

    load_stage(0, 0); CP_COMMIT();
    load_stage(1, 1); CP_COMMIT();

    for (int kb = 0; kb < NIT; kb++){
        CP_WAIT(1);
        __syncthreads();
        if (kb + 2 < NIT){
            load_stage(kb + 2, (kb + 2) % 3);
            CP_COMMIT();
        }

        const uint32_t stb = smb + (kb % 3) * STG_B;
#pragma unroll
        for (int kc = 0; kc < 4; kc++){
            const uint32_t k0b = kc * 32;        // 16 halves
            uint32_t fAr[4][4], fAi[4][4], bWr[2][4], bWi[2][4];
            ldsm4(bWr[0], stb + OWrB + boff[0] + k0b);
            ldsm4(bWr[1], stb + OWrB + boff[1] + k0b);
            ldsm4(bWi[0], stb + OWiB + boff[0] + k0b);
            ldsm4(bWi[1], stb + OWiB + boff[1] + k0b);
#pragma unroll
            for (int mi = 0; mi < 4; mi++){
                ldsm4(fAr[mi], stb + OArB + aoff[mi] + k0b);
                ldsm4(fAi[mi], stb + OAiB + aoff[mi] + k0b);
            }
#pragma unroll
            for (int nj = 0; nj < 4; nj++){
                const int P = nj >> 1, q = nj & 1;
                uint32_t br0 = bWr[P][q],     br1 = bWr[P][q + 2];
                uint32_t bi0 = bWi[P][q],     bi1 = bWi[P][q + 2];
                uint32_t bn0 = bi0 ^ 0x80008000u;   // -wi
                uint32_t bn1 = bi1 ^ 0x80008000u;
#pragma unroll
                for (int mi = 0; mi < 4; mi++){
                    mma16(accRe[mi][nj], fAr[mi], br0, br1);
                    mma16(accRe[mi][nj], fAi[mi], bn0, bn1);
                    mma16(accIm[mi][nj], fAr[mi], bi0, bi1);
                    mma16(accIm[mi][nj], fAi[mi], br0, br1);
                }
            }
        }
    }

    // ======================= fused epilogues =======================
    const float* b1rp = b1r + (size_t)g * Hd;
    const float* b1ip = b1i + (size_t)g * Hd;
    const float* b2rp = b2r + (size_t)g * Hd;
    const float* b2ip = b2i + (size_t)g * Hd;

#pragma unroll
    for (int nj = 0; nj < 4; nj++){
        const int n = nb + wn * 32 + nj * 8 + tig * 2;
        const float br0 = b1rp[n]     + b2rp[n];
        const float bi0 = b1ip[n]     + b2ip[n];
        const float br1 = b1rp[n + 1] + b2rp[n + 1];
        const float bi1 = b1ip[n + 1] + b2ip[n + 1];
#pragma unroll
        for (int mi = 0; mi < 4; mi++){
#pragma unroll
            for (int half = 0; half < 2; half++){
                const int row = mb + wm * 64 + mi * 16 + gid + half * 8;
                const size_t idx = (size_t)row * Hd + n;
                const float pr0 = accRe[mi][nj][half * 2]     + br0;
                const float pi0 = accIm[mi][nj][half * 2]     + bi0;
                const float pr1 = accRe[mi][nj][half * 2 + 1] + br1;
                const float pi1 = accIm[mi][nj][half * 2 + 1] + bi1;

                if (MODE == 1){
                    float v0r = sigm(pr0), v0i = sigm(pi0);
                    float v1r = sigm(pr1), v1i = sigm(pi1);
                    if (g == 0){
                        *(float4*)&zout[idx] = make_float4(v0r, v0i, v1r, v1i);
                    } else {
                        float2 hr = *(const float2*)&hre[idx];
                        float2 hi = *(const float2*)&him[idx];
                        __half2 rr = __floats2half2_rn(v0r * hr.x - v0i * hi.x,
                                                       v1r * hr.y - v1i * hi.y);
                        __half2 ri = __floats2half2_rn(v0r * hi.x + v0i * hr.x,
                                                       v1r * hi.y + v1i * hr.y);
                        *(__half2*)&rhre[idx] = rr;
                        *(__half2*)&rhim[idx] = ri;
                    }
                }
                else {  // MODE 2
                    float4 zv = *(const float4*)&zin[idx];
                    float2 hr = *(const float2*)&hre[idx];
                    float2 hi = *(const float2*)&him[idx];
                    float4 ov;
                    {
                        float tr = pr0, ti = pi0;
                        float mag = sqrtf(tr * tr + ti * ti);
                        float s = (mag > 0.f) ? (tanhf(mag) / mag) : 1.f;
                        float htr = s * tr, hti = s * ti;
                        float or_ = 1.f - zv.x, oi = -zv.y;
                        ov.x = or_ * hr.x - oi * hi.x + zv.x * htr - zv.y * hti;
                        ov.y = or_ * hi.x + oi * hr.x + zv.x * hti + zv.y * htr;
                    }
                    {
                        float tr = pr1, ti = pi1;
                        float mag = sqrtf(tr * tr + ti * ti);
                        float s = (mag > 0.f) ? (tanhf(mag) / mag) : 1.f;
                        float htr = s * tr, hti = s * ti;
                        float or_ = 1.f - zv.z, oi = -zv.w;
                        ov.z = or_ * hr.y - oi * hi.y + zv.z * htr - zv.w * hti;
                        ov.w = or_ * hi.y + oi * hr.y + zv.z * hti + zv.w * htr;
                    }
                    *(float4*)&outC[idx] = ov;
                }
            }
        }
    }
}

// ======================= prep: fp32 -> fp16, 4 planes per launch ==============
__global__ void to_fp16_multi(const float4* __restrict__ s0, const float4* __restrict__ s1,
                              const float4* __restrict__ s2, const float4* __restrict__ s3,
                              __half2* __restrict__ d0, __half2* __restrict__ d1,
                              __half2* __restrict__ d2, __half2* __restrict__ d3, int n4)
{
    int i = blockIdx.x * blockDim.x + threadIdx.x;
    if (i >= n4) return;
    const float4* s; __half2* d;
    switch (blockIdx.y){
        case 0:  s = s0; d = d0; break;
        case 1:  s = s1; d = d1; break;
        case 2:  s = s2; d = d2; break;
        default: s = s3; d = d3; break;
    }
    float4 v = s[i];
    d[i * 2]     = __floats2half2_rn(v.x, v.y);
    d[i * 2 + 1] = __floats2half2_rn(v.z, v.w);
}

// ======================= launch =======================
extern "C" void kernel_launch(void* const* d_in, const int* in_sizes, int n_in,
                              void* d_out, int out_size)
{
    const float* x_re  = (const float*)d_in[0];
    const float* x_im  = (const float*)d_in[1];
    const float* h_re  = (const float*)d_in[2];
    const float* h_im  = (const float*)d_in[3];
    const float* Wx_re = (const float*)d_in[4];
    const float* Wx_im = (const float*)d_in[5];
    const float* Wh_re = (const float*)d_in[6];
    const float* Wh_im = (const float*)d_in[7];
    const float* bx_re = (const float*)d_in[8];
    const float* bx_im = (const float*)d_in[9];
    const float* bh_re = (const float*)d_in[10];
    const float* bh_im = (const float*)d_in[11];

    float2* zbuf; cudaGetSymbolAddress((void**)&zbuf, g_z);
    __half *rhre, *rhim, *txr, *txi, *thr, *thi, *wxr, *wxi, *whr, *whi;
    cudaGetSymbolAddress((void**)&rhre, g_rh_re);
    cudaGetSymbolAddress((void**)&rhim, g_rh_im);
    cudaGetSymbolAddress((void**)&txr, g_tx_re);
    cudaGetSymbolAddress((void**)&txi, g_tx_im);
    cudaGetSymbolAddress((void**)&thr, g_th_re);
    cudaGetSymbolAddress((void**)&thi, g_th_im);
    cudaGetSymbolAddress((void**)&wxr, g_tWx_re);
    cudaGetSymbolAddress((void**)&wxi, g_tWx_im);
    cudaGetSymbolAddress((void**)&whr, g_tWh_re);
    cudaGetSymbolAddress((void**)&whi, g_tWh_im);

    cudaFuncSetAttribute(cgemm_fused<1>, cudaFuncAttributeMaxDynamicSharedMemorySize, SMEM_DYN);
    cudaFuncSetAttribute(cgemm_fused<2>, cudaFuncAttributeMaxDynamicSharedMemorySize, SMEM_DYN);

    const int nBH4 = (int)(BH / 4);
    const int nW4  = WSZ / 4;
    // prep (2 launches)
    to_fp16_multi<<<dim3((nBH4 + 255) / 256, 4), 256>>>(
        (const float4*)x_re, (const float4*)x_im, (const float4*)h_re, (const float4*)h_im,
        (__half2*)txr, (__half2*)txi, (__half2*)thr, (__half2*)thi, nBH4);
    to_fp16_multi<<<dim3((nW4 + 255) / 256, 4), 256>>>(
        (const float4*)Wx_re, (const float4*)Wx_im, (const float4*)Wh_re, (const float4*)Wh_im,
        (__half2*)wxr, (__half2*)wxi, (__half2*)whr, (__half2*)whi, nW4);

    dim3 blk(256);
    dim3 grid_zr(Hd / 128, Bsz / 128, 2);
    dim3 grid_f (Hd / 128, Bsz / 128, 1);

    // K1: z (g=0) and r -> r*h (g=1); K = [x | h] @ [Wx_g ; Wh_g]
    cgemm_fused<1><<<grid_zr, blk, SMEM_DYN>>>(
        txr, txi, thr, thi,
        wxr, wxi, whr, whi,
        bx_re, bx_im, bh_re, bh_im,
        h_re, h_im,
        nullptr, zbuf, rhre, rhim, nullptr);

    // K2: h_tilde & final mix; K = [x | r*h] @ [Wx_2 ; Wh_2]
    cgemm_fused<2><<<grid_f, blk, SMEM_DYN>>>(
        txr, txi, rhre, rhim,
        wxr + 2ull * Hd * Hd, wxi + 2ull * Hd * Hd,
        whr + 2ull * Hd * Hd, whi + 2ull * Hd * Hd,
        bx_re + 2 * Hd, bx_im + 2 * Hd, bh_re + 2 * Hd, bh_im + 2 * Hd,
        h_re, h_im,
        zbuf, nullptr, nullptr, nullptr, (float2*)d_out);
}

// round 15
// speedup vs baseline: 6.9041x; 1.0684x over previous
#include <cuda_runtime.h>
#include <cuda_fp16.h>
#include <cstdint>
#include <math.h>

static constexpr int Bsz = 16384;
static constexpr int Hd  = 512;
static constexpr long long BH = (long long)Bsz * Hd;   // 8388608
static constexpr int WSZ = 3 * Hd * Hd;

// -------- scratch (device globals; allocation-free rule) --------
__device__ float2 g_z  [(unsigned long long)Bsz * Hd];     // gate z (fp32 complex)
__device__ __half g_rh_re[(unsigned long long)Bsz * Hd];   // r*h planes (fp16)
__device__ __half g_rh_im[(unsigned long long)Bsz * Hd];
// fp16 copies of inputs
__device__ __half g_tx_re[(unsigned long long)Bsz * Hd];
__device__ __half g_tx_im[(unsigned long long)Bsz * Hd];
__device__ __half g_th_re[(unsigned long long)Bsz * Hd];
__device__ __half g_th_im[(unsigned long long)Bsz * Hd];
__device__ __half g_tWx_re[WSZ];
__device__ __half g_tWx_im[WSZ];
__device__ __half g_tWh_re[WSZ];
__device__ __half g_tWh_im[WSZ];

// ======================= PTX helpers (base-target only) =======================
__device__ __forceinline__ uint32_t smem_u32(const void* p){
    uint32_t a;
    asm("{ .reg .u64 t; cvta.to.shared.u64 t, %1; cvt.u32.u64 %0, t; }" : "=r"(a) : "l"(p));
    return a;
}
__device__ __forceinline__ void cp16(uint32_t dst, const void* src){
    asm volatile("cp.async.cg.shared.global [%0], [%1], 16;" :: "r"(dst), "l"(src));
}
#define CP_COMMIT() asm volatile("cp.async.commit_group;" ::: "memory")
#define CP_WAIT(n)  asm volatile("cp.async.wait_group %0;" :: "n"(n) : "memory")

__device__ __forceinline__ void ldsm4(uint32_t* r, uint32_t addr){
    asm volatile("ldmatrix.sync.aligned.m8n8.x4.shared.b16 {%0,%1,%2,%3}, [%4];"
        : "=r"(r[0]), "=r"(r[1]), "=r"(r[2]), "=r"(r[3]) : "r"(addr));
}
__device__ __forceinline__ void mma16(float* c, const uint32_t* a, uint32_t b0, uint32_t b1){
    asm volatile(
        "mma.sync.aligned.m16n8k16.row.col.f32.f16.f16.f32 "
        "{%0,%1,%2,%3}, {%4,%5,%6,%7}, {%8,%9}, {%0,%1,%2,%3};"
        : "+f"(c[0]), "+f"(c[1]), "+f"(c[2]), "+f"(c[3])
        : "r"(a[0]), "r"(a[1]), "r"(a[2]), "r"(a[3]), "r"(b0), "r"(b1));
}
__device__ __forceinline__ float sigm(float x) { return 1.0f / (1.0f + expf(-x)); }

// ======================= fused K=1024 complex GEMM ===========================
// acc[m][n] = sum_k A1[m][k]*W1[g][n][k] + A2[m][k]*W2[g][n][k]   (complex fp16)
// MODE 1: g=0 -> z = sigm(acc+b); g=1 -> r = sigm(acc+b), store r*h (fp16).
// MODE 2: final: h_tilde = polar_tanh(acc+b); out = (1-z)h + z*h_tilde.
// CTA 128x128, 16 warps (4M x 4N) of 32x32 warp tiles.
static constexpr int NIT  = 16;                  // 1024 / 64
static constexpr int RSB  = 144;                 // row stride bytes (72 halves)
static constexpr int OArB = 0;
static constexpr int OAiB = 128 * RSB;
static constexpr int OWrB = 256 * RSB;
static constexpr int OWiB = 384 * RSB;
static constexpr int STG_B = 512 * RSB;          // 73728
static constexpr int SMEM_DYN = 3 * STG_B;       // 221184

template<int MODE>
__global__ __launch_bounds__(512)
void cgemm_fused(const __half* __restrict__ A1r, const __half* __restrict__ A1i,
                 const __half* __restrict__ A2r, const __half* __restrict__ A2i,
                 const __half* __restrict__ W1r, const __half* __restrict__ W1i,
                 const __half* __restrict__ W2r, const __half* __restrict__ W2i,
                 const float* __restrict__ b1r, const float* __restrict__ b1i,
                 const float* __restrict__ b2r, const float* __restrict__ b2i,
                 const float* __restrict__ hre, const float* __restrict__ him,
                 const float2* __restrict__ zin, float2* __restrict__ zout,
                 __half* __restrict__ rhre, __half* __restrict__ rhim,
                 float2* __restrict__ outC)
{
    extern __shared__ __align__(16) char smc[];
    const int tid = threadIdx.x;
    const int w   = tid >> 5, l = tid & 31;
    const int gid = l >> 2, tig = l & 3;
    const int wm  = w & 3;                       // 0..3 (M, 32 each)
    const int wn  = w >> 2;                      // 0..3 (N, 32 each)
    const int g   = blockIdx.z;
    const int mb  = blockIdx.y * 128;
    const int nb  = blockIdx.x * 128;
    const uint32_t smb = smem_u32(smc);

    const size_t gofs = (size_t)g * Hd * Hd;
    const char* pW1r = (const char*)(W1r + gofs);
    const char* pW1i = (const char*)(W1i + gofs);
    const char* pW2r = (const char*)(W2r + gofs);
    const char* pW2i = (const char*)(W2i + gofs);

    // ldmatrix per-thread byte offsets
    const int l7 = l & 7, l8 = (l >> 3) & 1, l16 = (l >> 4) & 1;
    uint32_t aoff[2], boff[2];
#pragma unroll
    for (int mi = 0; mi < 2; mi++)
        aoff[mi] = (uint32_t)((wm * 32 + mi * 16 + l8 * 8 + l7) * RSB + l16 * 16);
#pragma unroll
    for (int P = 0; P < 2; P++)
        boff[P] = (uint32_t)((wn * 32 + P * 16 + l8 * 8 + l7) * RSB + l16 * 16);

    // loader: segment 0 = (A1, W1) for kb<8, segment 1 = (A2, W2) for kb>=8
    auto load_stage = [&](int kb, int st){
        const uint32_t base = smb + st * STG_B;
        const bool s1 = (kb >= 8);
        const char* Ar = s1 ? (const char*)A2r : (const char*)A1r;
        const char* Ai = s1 ? (const char*)A2i : (const char*)A1i;
        const char* Wr = s1 ? pW2r : pW1r;
        const char* Wi = s1 ? pW2i : pW1i;
        const size_t kby = (size_t)(kb & 7) * 128;   // 64 halves
#pragma unroll
        for (int i = 0; i < 8; i++){
            int c   = i * 512 + tid;
            int row = c >> 3;
            int j   = (c & 7) * 16;
            if (row < 128){
                cp16(base + OArB + row * RSB + j, Ar + (size_t)(mb + row) * 1024 + kby + j);
            } else if (row < 256){
                int r = row - 128;
                cp16(base + OAiB + r * RSB + j,   Ai + (size_t)(mb + r) * 1024 + kby + j);
            } else if (row < 384){
                int r = row - 256;
                cp16(base + OWrB + r * RSB + j,   Wr + (size_t)(nb + r) * 1024 + kby + j);
            } else {
                int r = row - 384;
                cp16(base + OWiB + r * RSB + j,   Wi + (size_t)(nb + r) * 1024 + kby + j);
            }
        }
    };

    float accRe[2][4][4], accIm[2][4][4];
#pragma unroll
    for (int mi = 0; mi < 2; mi++)
#pragma unroll
        for (int nj = 0; nj < 4; nj++)
#pragma unroll
            for (int q = 0; q < 4; q++){ accRe[mi][nj][q] = 0.f; accIm[mi][nj][q] = 0.f; }

    load_stage(0, 0); CP_COMMIT();
    load_stage(1, 1); CP_COMMIT();

    for (int kb = 0; kb < NIT; kb++){
        CP_WAIT(1);
        __syncthreads();
        if (kb + 2 < NIT){
            load_stage(kb + 2, (kb + 2) % 3);
            CP_COMMIT();
        }

        const uint32_t stb = smb + (kb % 3) * STG_B;
#pragma unroll
        for (int kc = 0; kc < 4; kc++){
            const uint32_t k0b = kc * 32;        // 16 halves
            uint32_t fAr[2][4], fAi[2][4], bWr[2][4], bWi[2][4];
            ldsm4(bWr[0], stb + OWrB + boff[0] + k0b);
            ldsm4(bWr[1], stb + OWrB + boff[1] + k0b);
            ldsm4(bWi[0], stb + OWiB + boff[0] + k0b);
            ldsm4(bWi[1], stb + OWiB + boff[1] + k0b);
#pragma unroll
            for (int mi = 0; mi < 2; mi++){
                ldsm4(fAr[mi], stb + OArB + aoff[mi] + k0b);
                ldsm4(fAi[mi], stb + OAiB + aoff[mi] + k0b);
            }
#pragma unroll
            for (int nj = 0; nj < 4; nj++){
                const int P = nj >> 1, q = nj & 1;
                uint32_t br0 = bWr[P][q],     br1 = bWr[P][q + 2];
                uint32_t bi0 = bWi[P][q],     bi1 = bWi[P][q + 2];
                uint32_t bn0 = bi0 ^ 0x80008000u;   // -wi
                uint32_t bn1 = bi1 ^ 0x80008000u;
#pragma unroll
                for (int mi = 0; mi < 2; mi++){
                    mma16(accRe[mi][nj], fAr[mi], br0, br1);
                    mma16(accRe[mi][nj], fAi[mi], bn0, bn1);
                    mma16(accIm[mi][nj], fAr[mi], bi0, bi1);
                    mma16(accIm[mi][nj], fAi[mi], br0, br1);
                }
            }
        }
    }

    // ======================= fused epilogues =======================
    const float* b1rp = b1r + (size_t)g * Hd;
    const float* b1ip = b1i + (size_t)g * Hd;
    const float* b2rp = b2r + (size_t)g * Hd;
    const float* b2ip = b2i + (size_t)g * Hd;

#pragma unroll
    for (int nj = 0; nj < 4; nj++){
        const int n = nb + wn * 32 + nj * 8 + tig * 2;
        const float br0 = b1rp[n]     + b2rp[n];
        const float bi0 = b1ip[n]     + b2ip[n];
        const float br1 = b1rp[n + 1] + b2rp[n + 1];
        const float bi1 = b1ip[n + 1] + b2ip[n + 1];
#pragma unroll
        for (int mi = 0; mi < 2; mi++){
#pragma unroll
            for (int half = 0; half < 2; half++){
                const int row = mb + wm * 32 + mi * 16 + gid + half * 8;
                const size_t idx = (size_t)row * Hd + n;
                const float pr0 = accRe[mi][nj][half * 2]     + br0;
                const float pi0 = accIm[mi][nj][half * 2]     + bi0;
                const float pr1 = accRe[mi][nj][half * 2 + 1] + br1;
                const float pi1 = accIm[mi][nj][half * 2 + 1] + bi1;

                if (MODE == 1){
                    float v0r = sigm(pr0), v0i = sigm(pi0);
                    float v1r = sigm(pr1), v1i = sigm(pi1);
                    if (g == 0){
                        *(float4*)&zout[idx] = make_float4(v0r, v0i, v1r, v1i);
                    } else {
                        float2 hr = *(const float2*)&hre[idx];
                        float2 hi = *(const float2*)&him[idx];
                        __half2 rr = __floats2half2_rn(v0r * hr.x - v0i * hi.x,
                                                       v1r * hr.y - v1i * hi.y);
                        __half2 ri = __floats2half2_rn(v0r * hi.x + v0i * hr.x,
                                                       v1r * hi.y + v1i * hr.y);
                        *(__half2*)&rhre[idx] = rr;
                        *(__half2*)&rhim[idx] = ri;
                    }
                }
                else {  // MODE 2
                    float4 zv = *(const float4*)&zin[idx];
                    float2 hr = *(const float2*)&hre[idx];
                    float2 hi = *(const float2*)&him[idx];
                    float4 ov;
                    {
                        float tr = pr0, ti = pi0;
                        float mag = sqrtf(tr * tr + ti * ti);
                        float s = (mag > 0.f) ? (tanhf(mag) / mag) : 1.f;
                        float htr = s * tr, hti = s * ti;
                        float or_ = 1.f - zv.x, oi = -zv.y;
                        ov.x = or_ * hr.x - oi * hi.x + zv.x * htr - zv.y * hti;
                        ov.y = or_ * hi.x + oi * hr.x + zv.x * hti + zv.y * htr;
                    }
                    {
                        float tr = pr1, ti = pi1;
                        float mag = sqrtf(tr * tr + ti * ti);
                        float s = (mag > 0.f) ? (tanhf(mag) / mag) : 1.f;
                        float htr = s * tr, hti = s * ti;
                        float or_ = 1.f - zv.z, oi = -zv.w;
                        ov.z = or_ * hr.y - oi * hi.y + zv.z * htr - zv.w * hti;
                        ov.w = or_ * hi.y + oi * hr.y + zv.z * hti + zv.w * htr;
                    }
                    *(float4*)&outC[idx] = ov;
                }
            }
        }
    }
}

// ======================= prep: fp32 -> fp16, 4 planes per launch ==============
__global__ void to_fp16_multi(const float4* __restrict__ s0, const float4* __restrict__ s1,
                              const float4* __restrict__ s2, const float4* __restrict__ s3,
                              __half2* __restrict__ d0, __half2* __restrict__ d1,
                              __half2* __restrict__ d2, __half2* __restrict__ d3, int n4)
{
    int i = blockIdx.x * blockDim.x + threadIdx.x;
    if (i >= n4) return;
    const float4* s; __half2* d;
    switch (blockIdx.y){
        case 0:  s = s0; d = d0; break;
        case 1:  s = s1; d = d1; break;
        case 2:  s = s2; d = d2; break;
        default: s = s3; d = d3; break;
    }
    float4 v = s[i];
    d[i * 2]     = __floats2half2_rn(v.x, v.y);
    d[i * 2 + 1] = __floats2half2_rn(v.z, v.w);
}

// ======================= launch =======================
extern "C" void kernel_launch(void* const* d_in, const int* in_sizes, int n_in,
                              void* d_out, int out_size)
{
    const float* x_re  = (const float*)d_in[0];
    const float* x_im  = (const float*)d_in[1];
    const float* h_re  = (const float*)d_in[2];
    const float* h_im  = (const float*)d_in[3];
    const float* Wx_re = (const float*)d_in[4];
    const float* Wx_im = (const float*)d_in[5];
    const float* Wh_re = (const float*)d_in[6];
    const float* Wh_im = (const float*)d_in[7];
    const float* bx_re = (const float*)d_in[8];
    const float* bx_im = (const float*)d_in[9];
    const float* bh_re = (const float*)d_in[10];
    const float* bh_im = (const float*)d_in[11];

    float2* zbuf; cudaGetSymbolAddress((void**)&zbuf, g_z);
    __half *rhre, *rhim, *txr, *txi, *thr, *thi, *wxr, *wxi, *whr, *whi;
    cudaGetSymbolAddress((void**)&rhre, g_rh_re);
    cudaGetSymbolAddress((void**)&rhim, g_rh_im);
    cudaGetSymbolAddress((void**)&txr, g_tx_re);
    cudaGetSymbolAddress((void**)&txi, g_tx_im);
    cudaGetSymbolAddress((void**)&thr, g_th_re);
    cudaGetSymbolAddress((void**)&thi, g_th_im);
    cudaGetSymbolAddress((void**)&wxr, g_tWx_re);
    cudaGetSymbolAddress((void**)&wxi, g_tWx_im);
    cudaGetSymbolAddress((void**)&whr, g_tWh_re);
    cudaGetSymbolAddress((void**)&whi, g_tWh_im);

    cudaFuncSetAttribute(cgemm_fused<1>, cudaFuncAttributeMaxDynamicSharedMemorySize, SMEM_DYN);
    cudaFuncSetAttribute(cgemm_fused<2>, cudaFuncAttributeMaxDynamicSharedMemorySize, SMEM_DYN);

    const int nBH4 = (int)(BH / 4);
    const int nW4  = WSZ / 4;
    to_fp16_multi<<<dim3((nBH4 + 255) / 256, 4), 256>>>(
        (const float4*)x_re, (const float4*)x_im, (const float4*)h_re, (const float4*)h_im,
        (__half2*)txr, (__half2*)txi, (__half2*)thr, (__half2*)thi, nBH4);
    to_fp16_multi<<<dim3((nW4 + 255) / 256, 4), 256>>>(
        (const float4*)Wx_re, (const float4*)Wx_im, (const float4*)Wh_re, (const float4*)Wh_im,
        (__half2*)wxr, (__half2*)wxi, (__half2*)whr, (__half2*)whi, nW4);

    dim3 blk(512);
    dim3 grid_zr(Hd / 128, Bsz / 128, 2);
    dim3 grid_f (Hd / 128, Bsz / 128, 1);

    // K1: z (g=0) and r -> r*h (g=1); K = [x | h] @ [Wx_g ; Wh_g]
    cgemm_fused<1><<<grid_zr, blk, SMEM_DYN>>>(
        txr, txi, thr, thi,
        wxr, wxi, whr, whi,
        bx_re, bx_im, bh_re, bh_im,
        h_re, h_im,
        nullptr, zbuf, rhre, rhim, nullptr);

    // K2: h_tilde & final mix; K = [x | r*h] @ [Wx_2 ; Wh_2]
    cgemm_fused<2><<<grid_f, blk, SMEM_DYN>>>(
        txr, txi, rhre, rhim,
        wxr + 2ull * Hd * Hd, wxi + 2ull * Hd * Hd,
        whr + 2ull * Hd * Hd, whi + 2ull * Hd * Hd,
        bx_re + 2 * Hd, bx_im + 2 * Hd, bh_re + 2 * Hd, bh_im + 2 * Hd,
        h_re, h_im,
        zbuf, nullptr, nullptr, nullptr, (float2*)d_out);
}